// round 1
// baseline (speedup 1.0000x reference)
#include <cuda_runtime.h>
#include <math.h>

#define L      40
#define BATCH  128
#define HIDI   512
#define H      512
#define G4     2048
#define NCLS   7000
#define HW     256
#define M5     (L*BATCH)   /* 5120 */
#define KCAT   1024

// ---------------- scratch (static device globals: no allocation) ----------------
__device__ float g_xts[M5*HIDI];                 // 10.5 MB
__device__ float g_xg [M5*G4];                   // 42 MB
__device__ float g_cat[M5*KCAT];                 // 21 MB  (cols 0..511 = h, 512..1023 = att)
__device__ float g_hem[M5*H];                    // 10.5 MB
__device__ float g_fatt[M5*HW];                  // 5.2 MB
__device__ float g_c  [BATCH*H];                 // LSTM cell state
__device__ float g_logits[(size_t)M5*NCLS];      // 143 MB

__device__ __forceinline__ float tanh_approx(float x) {
    float y;
    asm("tanh.approx.f32 %0, %1;" : "=f"(y) : "f"(x));
    return y;
}
__device__ __forceinline__ float sigmoid_acc(float x) {
    return 1.0f / (1.0f + expf(-x));
}

// ---------------- K0: gather teacher-forced inputs ----------------
// xts[m= l*B+b][k] = (l==0) ? hidden_en[0,b,k] : embed_w[target[b, l-1], k]
__global__ void gather_kernel(const float* __restrict__ hidden_en,
                              const float* __restrict__ embed_w,
                              const int*   __restrict__ target) {
    const int m = blockIdx.x;
    const int l = m / BATCH, b = m % BATCH;
    const int k = threadIdx.x * 4;
    const float* src = (l == 0)
        ? (hidden_en + (size_t)b * HIDI)
        : (embed_w   + (size_t)target[b * L + (l - 1)] * HIDI);
    *(float4*)&g_xts[(size_t)m * HIDI + k] = *(const float4*)&src[k];
}

// ---------------- generic fp32 GEMM:  C[m][n] = bias[n] + sum_k A[m][k]*B[n][k] ----------------
// 128x128 block tile, 8 K-chunk, 256 threads, 8x8 per-thread micro-tile.
// M is always a multiple of 128 here; K a multiple of 8; only N needs guards.
__global__ void sgemm_nt_bias(const float* __restrict__ A, int lda,
                              const float* __restrict__ B, int ldb,
                              const float* __restrict__ bias,
                              float* __restrict__ C, int ldc,
                              int N, int K) {
    __shared__ float As[8][128];
    __shared__ float Bs[8][128];
    const int bm = blockIdx.y * 128;
    const int bn = blockIdx.x * 128;
    const int tid = threadIdx.x;
    const int tx = tid % 16, ty = tid / 16;
    const int lr = tid >> 1;          // row within tile (0..127)
    const int lk = (tid & 1) * 4;     // k sub-offset (0 or 4)

    float acc[8][8];
#pragma unroll
    for (int i = 0; i < 8; i++)
#pragma unroll
        for (int j = 0; j < 8; j++) acc[i][j] = 0.0f;

    for (int k0 = 0; k0 < K; k0 += 8) {
        float4 av = *(const float4*)&A[(size_t)(bm + lr) * lda + k0 + lk];
        float4 bv = make_float4(0.f, 0.f, 0.f, 0.f);
        int brow = bn + lr;
        if (brow < N) bv = *(const float4*)&B[(size_t)brow * ldb + k0 + lk];
        __syncthreads();
        As[lk+0][lr] = av.x; As[lk+1][lr] = av.y; As[lk+2][lr] = av.z; As[lk+3][lr] = av.w;
        Bs[lk+0][lr] = bv.x; Bs[lk+1][lr] = bv.y; Bs[lk+2][lr] = bv.z; Bs[lk+3][lr] = bv.w;
        __syncthreads();
#pragma unroll
        for (int kk = 0; kk < 8; kk++) {
            float4 a0 = *(const float4*)&As[kk][ty*8];
            float4 a1 = *(const float4*)&As[kk][ty*8+4];
            float4 b0 = *(const float4*)&Bs[kk][tx*8];
            float4 b1 = *(const float4*)&Bs[kk][tx*8+4];
            float ra[8] = {a0.x,a0.y,a0.z,a0.w,a1.x,a1.y,a1.z,a1.w};
            float rb[8] = {b0.x,b0.y,b0.z,b0.w,b1.x,b1.y,b1.z,b1.w};
#pragma unroll
            for (int i = 0; i < 8; i++)
#pragma unroll
                for (int j = 0; j < 8; j++) acc[i][j] += ra[i]*rb[j];
        }
    }
#pragma unroll
    for (int i = 0; i < 8; i++) {
        int row = bm + ty*8 + i;
#pragma unroll
        for (int j = 0; j < 8; j++) {
            int col = bn + tx*8 + j;
            if (col < N) C[(size_t)row * ldc + col] = acc[i][j] + bias[col];
        }
    }
}

// ---------------- K2: one LSTM step (gates GEMM fused with pointwise) ----------------
// grid (512/16 d-tiles, 128/32 b-tiles), 256 threads.
// thread (tx=d, ty) computes 4 gates for rows b0+ty and b0+ty+16.
__global__ void lstm_step(const float* __restrict__ W_hh,
                          const float* __restrict__ b_hh, int l) {
    __shared__ float sh_h[32][33];
    __shared__ float sh_w[4][16][33];
    const int tid = threadIdx.x;
    const int tx = tid % 16;
    const int ty = tid / 16;
    const int d0 = blockIdx.x * 16;
    const int b0 = blockIdx.y * 32;

    float acc[4][2];
#pragma unroll
    for (int q = 0; q < 4; q++) {
        float bb = b_hh[q*H + d0 + tx];
        acc[q][0] = g_xg[(size_t)(l*BATCH + b0 + ty     ) * G4 + q*H + d0 + tx] + bb;
        acc[q][1] = g_xg[(size_t)(l*BATCH + b0 + ty + 16) * G4 + q*H + d0 + tx] + bb;
    }
    for (int k0 = 0; k0 < H; k0 += 32) {
        __syncthreads();
#pragma unroll
        for (int i = 0; i < 4; i++) {                 // h tile: 32 b x 32 k
            int e = tid + i*256;
            int bb_ = e >> 5, kk = e & 31;
            float v = 0.0f;
            if (l > 0) v = g_cat[(size_t)((l-1)*BATCH + b0 + bb_) * KCAT + k0 + kk];
            sh_h[bb_][kk] = v;
        }
#pragma unroll
        for (int i = 0; i < 8; i++) {                 // W tile: 4 gates x 16 d x 32 k
            int e = tid + i*256;
            int q = e >> 9; int r = e & 511;
            int dd = r >> 5, kk = r & 31;
            sh_w[q][dd][kk] = W_hh[(size_t)(q*H + d0 + dd) * H + k0 + kk];
        }
        __syncthreads();
#pragma unroll
        for (int kk = 0; kk < 32; kk++) {
            float h1 = sh_h[ty][kk], h2 = sh_h[ty+16][kk];
#pragma unroll
            for (int q = 0; q < 4; q++) {
                float w = sh_w[q][tx][kk];
                acc[q][0] += h1 * w;
                acc[q][1] += h2 * w;
            }
        }
    }
#pragma unroll
    for (int r = 0; r < 2; r++) {
        int b = b0 + ty + r*16;
        int d = d0 + tx;
        float ig = sigmoid_acc(acc[0][r]);
        float fg = sigmoid_acc(acc[1][r]);
        float gg = tanhf(acc[2][r]);
        float og = sigmoid_acc(acc[3][r]);
        float cp = (l > 0) ? g_c[b*H + d] : 0.0f;
        float cn = fg*cp + ig*gg;
        float hn = og * tanhf(cn);
        g_c[b*H + d] = cn;
        g_cat[(size_t)(l*BATCH + b) * KCAT + d] = hn;
    }
}

// ---------------- K4a: feat_att[l,b,n] = sum_c tanh(x_em[b,c,n]+hem[l,b,c])*attw[c] + attw_b ----
// grid (16 n-chunks of 16, 128 b), 256 threads. x_em chunk loaded once, reused over all 40 l.
__global__ void featatt_kernel(const float* __restrict__ x_em,
                               const float* __restrict__ attw_w,
                               const float* __restrict__ attw_b) {
    __shared__ float sx[512][17];
    __shared__ float sh_hem[512];
    __shared__ float sh_w[512];
    __shared__ float red[16][17];
    const int tid = threadIdx.x;
    const int b  = blockIdx.y;
    const int n0 = blockIdx.x * 16;
#pragma unroll
    for (int i = 0; i < 32; i++) {
        int e = tid + i*256;
        int c = e >> 4, j = e & 15;
        sx[c][j] = x_em[((size_t)b*512 + c) * 256 + n0 + j];
    }
    sh_w[tid]     = attw_w[tid];
    sh_w[tid+256] = attw_w[tid+256];
    const float ab = attw_b[0];
    const int j  = tid % 16;
    const int cg = tid / 16;
    for (int l = 0; l < L; l++) {
        __syncthreads();
        sh_hem[tid]     = g_hem[(size_t)(l*BATCH + b) * H + tid];
        sh_hem[tid+256] = g_hem[(size_t)(l*BATCH + b) * H + tid + 256];
        __syncthreads();
        float acc = 0.0f;
#pragma unroll 8
        for (int i = 0; i < 32; i++) {
            int c = cg*32 + i;
            acc += tanh_approx(sx[c][j] + sh_hem[c]) * sh_w[c];
        }
        red[cg][j] = acc;
        __syncthreads();
        if (tid < 16) {
            float s = 0.0f;
#pragma unroll
            for (int i = 0; i < 16; i++) s += red[i][tid];
            g_fatt[(size_t)(l*BATCH + b) * HW + n0 + tid] = s + ab;
        }
    }
}

// ---------------- K4b: softmax over n (per l) + att = alpha @ att_x_em ----------------
// grid (128 b), 256 threads. alpha for all 40 l staged in smem; att_x_em[b] streamed once.
__global__ void attred_kernel(const float* __restrict__ att_x_em) {
    __shared__ float s_alpha[L][HW];   // 40 KB
    __shared__ float s_red[8];
    __shared__ float s_val;
    const int tid = threadIdx.x;
    const int b = blockIdx.x;
    const int lane = tid & 31, wid = tid >> 5;
    for (int l = 0; l < L; l++) {
        float v = g_fatt[(size_t)(l*BATCH + b) * HW + tid];
        float m = v;
#pragma unroll
        for (int o = 16; o > 0; o >>= 1) m = fmaxf(m, __shfl_xor_sync(~0u, m, o));
        if (lane == 0) s_red[wid] = m;
        __syncthreads();
        if (tid == 0) {
            float mm = s_red[0];
#pragma unroll
            for (int i = 1; i < 8; i++) mm = fmaxf(mm, s_red[i]);
            s_val = mm;
        }
        __syncthreads();
        float e = __expf(v - s_val);
        float s = e;
#pragma unroll
        for (int o = 16; o > 0; o >>= 1) s += __shfl_xor_sync(~0u, s, o);
        if (lane == 0) s_red[wid] = s;
        __syncthreads();
        if (tid == 0) {
            float ss = 0.0f;
#pragma unroll
            for (int i = 0; i < 8; i++) ss += s_red[i];
            s_val = ss;
        }
        __syncthreads();
        s_alpha[l][tid] = e / s_val;
        __syncthreads();
    }
    float acc[L][2];
#pragma unroll
    for (int l = 0; l < L; l++) { acc[l][0] = 0.0f; acc[l][1] = 0.0f; }
    const float* axb = att_x_em + (size_t)b * HW * H;
    for (int n = 0; n < HW; n++) {
        float2 ax = *(const float2*)&axb[(size_t)n * H + 2*tid];
#pragma unroll
        for (int l = 0; l < L; l++) {
            float a = s_alpha[l][n];
            acc[l][0] += a * ax.x;
            acc[l][1] += a * ax.y;
        }
    }
#pragma unroll
    for (int l = 0; l < L; l++) {
        size_t o = (size_t)(l*BATCH + b) * KCAT + 512 + 2*tid;
        *(float2*)&g_cat[o] = make_float2(acc[l][0], acc[l][1]);
    }
}

// ---------------- K6: row log-softmax over 7000 classes, write [B,L,NCLS] ----------------
__global__ void logsoftmax_kernel(float* __restrict__ out) {
    const int m = blockIdx.x;
    const int l = m / BATCH, b = m % BATCH;
    const int tid = threadIdx.x;
    const int lane = tid & 31, wid = tid >> 5;
    __shared__ float s_red[8];
    __shared__ float s_val;
    float vals[28];
    const float* row = g_logits + (size_t)m * NCLS;
#pragma unroll
    for (int i = 0; i < 28; i++) {
        int idx = tid + i*256;
        vals[i] = (idx < NCLS) ? row[idx] : -1e30f;
    }
    float mx = -1e30f;
#pragma unroll
    for (int i = 0; i < 28; i++) mx = fmaxf(mx, vals[i]);
#pragma unroll
    for (int o = 16; o > 0; o >>= 1) mx = fmaxf(mx, __shfl_xor_sync(~0u, mx, o));
    if (lane == 0) s_red[wid] = mx;
    __syncthreads();
    if (tid == 0) {
        float mm = s_red[0];
#pragma unroll
        for (int i = 1; i < 8; i++) mm = fmaxf(mm, s_red[i]);
        s_val = mm;
    }
    __syncthreads();
    const float mall = s_val;
    float sum = 0.0f;
#pragma unroll
    for (int i = 0; i < 28; i++) sum += __expf(vals[i] - mall);
#pragma unroll
    for (int o = 16; o > 0; o >>= 1) sum += __shfl_xor_sync(~0u, sum, o);
    if (lane == 0) s_red[wid] = sum;
    __syncthreads();
    if (tid == 0) {
        float ss = 0.0f;
#pragma unroll
        for (int i = 0; i < 8; i++) ss += s_red[i];
        s_val = ss;
    }
    __syncthreads();
    const float lse = mall + logf(s_val);
    float* orow = out + ((size_t)b * L + l) * NCLS;
#pragma unroll
    for (int i = 0; i < 28; i++) {
        int idx = tid + i*256;
        if (idx < NCLS) orow[idx] = vals[i] - lse;
    }
}

// ---------------- launch ----------------
extern "C" void kernel_launch(void* const* d_in, const int* in_sizes, int n_in,
                              void* d_out, int out_size) {
    const float* hidden_en = (const float*)d_in[0];
    const float* x_em      = (const float*)d_in[1];
    const float* att_x_em  = (const float*)d_in[2];
    const int*   target    = (const int*)  d_in[3];
    // d_in[4], d_in[5] = feature_h, feature_w (compile-time constants here)
    const float* embed_w = (const float*)d_in[6];
    const float* W_ih    = (const float*)d_in[7];
    const float* W_hh    = (const float*)d_in[8];
    const float* b_ih    = (const float*)d_in[9];
    const float* b_hh    = (const float*)d_in[10];
    const float* hem_w   = (const float*)d_in[11];
    const float* hem_b   = (const float*)d_in[12];
    const float* attw_w  = (const float*)d_in[13];
    const float* attw_b  = (const float*)d_in[14];
    const float* lin_w   = (const float*)d_in[15];
    const float* lin_b   = (const float*)d_in[16];
    float* out = (float*)d_out;

    void *p_xts, *p_xg, *p_cat, *p_hem, *p_logits;
    cudaGetSymbolAddress(&p_xts,    g_xts);
    cudaGetSymbolAddress(&p_xg,     g_xg);
    cudaGetSymbolAddress(&p_cat,    g_cat);
    cudaGetSymbolAddress(&p_hem,    g_hem);
    cudaGetSymbolAddress(&p_logits, g_logits);

    // K0: gather teacher-forced inputs
    gather_kernel<<<M5, 128>>>(hidden_en, embed_w, target);

    // K1: xg_all = xts @ W_ih^T + b_ih   [5120 x 2048], K=512
    sgemm_nt_bias<<<dim3(G4/128, M5/128), 256>>>(
        (const float*)p_xts, HIDI, W_ih, HIDI, b_ih, (float*)p_xg, G4, G4, HIDI);

    // K2: sequential LSTM (writes h into g_cat cols 0..511)
    for (int l = 0; l < L; l++)
        lstm_step<<<dim3(H/16, BATCH/32), 256>>>(W_hh, b_hh, l);

    // K3: hem = H_all @ hem_w^T + hem_b   [5120 x 512], K=512 (A = g_cat, lda=1024)
    sgemm_nt_bias<<<dim3(H/128, M5/128), 256>>>(
        (const float*)p_cat, KCAT, hem_w, H, hem_b, (float*)p_hem, H, H, H);

    // K4a: feat_att  (x_em read exactly once)
    featatt_kernel<<<dim3(16, BATCH), 256>>>(x_em, attw_w, attw_b);

    // K4b: softmax + att (att_x_em read exactly once); writes g_cat cols 512..1023
    attred_kernel<<<BATCH, 256>>>(att_x_em);

    // K5: logits = [h, att] @ lin_w^T + lin_b   [5120 x 7000], K=1024
    sgemm_nt_bias<<<dim3((NCLS+127)/128, M5/128), 256>>>(
        (const float*)p_cat, KCAT, lin_w, KCAT, lin_b, (float*)p_logits, NCLS, NCLS, KCAT);

    // K6: log-softmax + transpose to [B, L, NCLS]
    logsoftmax_kernel<<<M5, 256>>>(out);
}

// round 2
// speedup vs baseline: 1.3860x; 1.3860x over previous
#include <cuda_runtime.h>
#include <math.h>

#define L      40
#define BATCH  128
#define HIDI   512
#define H      512
#define G4     2048
#define NCLS   7000
#define HW     256
#define M5     (L*BATCH)   /* 5120 */
#define KCAT   1024

// ---------------- scratch (static device globals: no allocation) ----------------
__device__ float g_xts[M5*HIDI];
__device__ float g_xg [M5*G4];
__device__ float g_cat[M5*KCAT];                 // cols 0..511 = h, 512..1023 = att
__device__ float g_hem[M5*H];
__device__ float g_fatt[M5*HW];
__device__ float g_c  [BATCH*H];
__device__ float g_part[4*BATCH*G4];             // LSTM k-split partials
__device__ float g_logits[(size_t)M5*NCLS];

__device__ __forceinline__ float tanh_approx(float x) {
    float y;
    asm("tanh.approx.f32 %0, %1;" : "=f"(y) : "f"(x));
    return y;
}
__device__ __forceinline__ float sigmoid_acc(float x) {
    return 1.0f / (1.0f + expf(-x));
}
// packed f32x2 helpers (Blackwell FFMA2 path)
__device__ __forceinline__ unsigned long long dup2(float x) {
    unsigned long long r;
    asm("mov.b64 %0, {%1, %1};" : "=l"(r) : "f"(x));
    return r;
}
__device__ __forceinline__ void fma2(unsigned long long& d, unsigned long long a, unsigned long long b) {
    asm("fma.rn.f32x2 %0, %1, %2, %0;" : "+l"(d) : "l"(a), "l"(b));
}
__device__ __forceinline__ float2 unpk(unsigned long long v) {
    float2 f;
    asm("mov.b64 {%0, %1}, %2;" : "=f"(f.x), "=f"(f.y) : "l"(v));
    return f;
}

// ---------------- K0: gather teacher-forced inputs ----------------
__global__ void gather_kernel(const float* __restrict__ hidden_en,
                              const float* __restrict__ embed_w,
                              const int*   __restrict__ target) {
    const int m = blockIdx.x;
    const int l = m / BATCH, b = m % BATCH;
    const int k = threadIdx.x * 4;
    const float* src = (l == 0)
        ? (hidden_en + (size_t)b * HIDI)
        : (embed_w   + (size_t)target[b * L + (l - 1)] * HIDI);
    *(float4*)&g_xts[(size_t)m * HIDI + k] = *(const float4*)&src[k];
}

// ---------------- f32x2 GEMM:  C[m][n] = bias[n] + sum_k A[m][k]*B[n][k] ----------------
// 256x128 block tile, K-chunk 8, 256 threads, 16x8 per-thread micro-tile
// with M packed in f32x2 pairs. M must be a multiple of 256; K multiple of 8.
__global__ void __launch_bounds__(256) sgemm2_nt_bias(
        const float* __restrict__ A, int lda,
        const float* __restrict__ B, int ldb,
        const float* __restrict__ bias,
        float* __restrict__ C, int ldc,
        int N, int K) {
    __shared__ float As[8][264];   // 256 + 8 pad (row = 1056B, 16B aligned)
    __shared__ float Bs[8][136];   // 128 + 8 pad (row = 544B, 16B aligned)
    const int bm = blockIdx.y * 256;
    const int bn = blockIdx.x * 128;
    const int tid = threadIdx.x;
    const int tx = tid & 15, ty = tid >> 4;
    const int rA = tid >> 1, kqA = (tid & 1) * 4;
    const int rB = tid & 127, kqB = (tid >> 7) * 4;

    unsigned long long acc[64];
#pragma unroll
    for (int i = 0; i < 64; i++) acc[i] = 0ULL;

    float4 ra0, ra1, rb;
    {   // prefetch chunk 0
        ra0 = *(const float4*)&A[(size_t)(bm + rA      ) * lda + kqA];
        ra1 = *(const float4*)&A[(size_t)(bm + 128 + rA) * lda + kqA];
        int br = bn + rB;
        rb = (br < N) ? *(const float4*)&B[(size_t)br * ldb + kqB]
                      : make_float4(0.f, 0.f, 0.f, 0.f);
    }

    for (int k0 = 0; k0 < K; k0 += 8) {
        __syncthreads();
        As[kqA+0][rA] = ra0.x; As[kqA+1][rA] = ra0.y; As[kqA+2][rA] = ra0.z; As[kqA+3][rA] = ra0.w;
        As[kqA+0][128+rA] = ra1.x; As[kqA+1][128+rA] = ra1.y; As[kqA+2][128+rA] = ra1.z; As[kqA+3][128+rA] = ra1.w;
        Bs[kqB+0][rB] = rb.x; Bs[kqB+1][rB] = rb.y; Bs[kqB+2][rB] = rb.z; Bs[kqB+3][rB] = rb.w;
        __syncthreads();
        if (k0 + 8 < K) {   // prefetch next chunk (overlaps with compute below)
            ra0 = *(const float4*)&A[(size_t)(bm + rA      ) * lda + k0 + 8 + kqA];
            ra1 = *(const float4*)&A[(size_t)(bm + 128 + rA) * lda + k0 + 8 + kqA];
            int br = bn + rB;
            rb = (br < N) ? *(const float4*)&B[(size_t)br * ldb + k0 + 8 + kqB]
                          : make_float4(0.f, 0.f, 0.f, 0.f);
        }
#pragma unroll
        for (int kk = 0; kk < 8; kk++) {
            ulonglong2 a0 = *(const ulonglong2*)&As[kk][ty*16 + 0];
            ulonglong2 a1 = *(const ulonglong2*)&As[kk][ty*16 + 4];
            ulonglong2 a2 = *(const ulonglong2*)&As[kk][ty*16 + 8];
            ulonglong2 a3 = *(const ulonglong2*)&As[kk][ty*16 + 12];
            float4 b0 = *(const float4*)&Bs[kk][tx*4];
            float4 b1 = *(const float4*)&Bs[kk][64 + tx*4];
            unsigned long long ap[8] = {a0.x, a0.y, a1.x, a1.y, a2.x, a2.y, a3.x, a3.y};
            float bf[8] = {b0.x, b0.y, b0.z, b0.w, b1.x, b1.y, b1.z, b1.w};
#pragma unroll
            for (int j = 0; j < 8; j++) {
                unsigned long long bd = dup2(bf[j]);
#pragma unroll
                for (int ip = 0; ip < 8; ip++) fma2(acc[ip*8 + j], ap[ip], bd);
            }
        }
    }

    // epilogue: unpack pairs (rows), add bias, vectorized stores
    const int c0 = bn + tx*4;
    const int c1 = bn + 64 + tx*4;
    float4 bb0 = make_float4(0.f,0.f,0.f,0.f), bb1 = bb0;
    if (c0 < N) bb0 = *(const float4*)&bias[c0];
    if (c1 < N) bb1 = *(const float4*)&bias[c1];
#pragma unroll
    for (int ip = 0; ip < 8; ip++) {
        const int r = bm + ty*16 + ip*2;
        float2 p0 = unpk(acc[ip*8+0]), p1 = unpk(acc[ip*8+1]);
        float2 p2 = unpk(acc[ip*8+2]), p3 = unpk(acc[ip*8+3]);
        float2 p4 = unpk(acc[ip*8+4]), p5 = unpk(acc[ip*8+5]);
        float2 p6 = unpk(acc[ip*8+6]), p7 = unpk(acc[ip*8+7]);
        if (c0 < N) {
            *(float4*)&C[(size_t)r*ldc + c0]     = make_float4(p0.x+bb0.x, p1.x+bb0.y, p2.x+bb0.z, p3.x+bb0.w);
            *(float4*)&C[(size_t)(r+1)*ldc + c0] = make_float4(p0.y+bb0.x, p1.y+bb0.y, p2.y+bb0.z, p3.y+bb0.w);
        }
        if (c1 < N) {
            *(float4*)&C[(size_t)r*ldc + c1]     = make_float4(p4.x+bb1.x, p5.x+bb1.y, p6.x+bb1.z, p7.x+bb1.w);
            *(float4*)&C[(size_t)(r+1)*ldc + c1] = make_float4(p4.y+bb1.x, p5.y+bb1.y, p6.y+bb1.z, p7.y+bb1.w);
        }
    }
}

// ---------------- LSTM step, phase 1: K-split partial GEMM ----------------
// partial[s][b][n] = sum_{k in split s} h_prev[b][k] * W_hh[n][k]
// grid (16 n-tiles, 2 m-tiles, 4 k-splits) = 128 blocks, 256 threads, 64x128 tile, 4x8 micro.
__global__ void __launch_bounds__(256) lstm_gemm_part(const float* __restrict__ W_hh, int l) {
    __shared__ float As[16][68];
    __shared__ float Bs[16][136];
    const int tid = threadIdx.x;
    const int bn = blockIdx.x * 128;
    const int bm = blockIdx.y * 64;
    const int ks = blockIdx.z;
    const int tx = tid & 15, ty = tid >> 4;
    const int rA = tid >> 2, kqA = (tid & 3) * 4;
    const int rB = tid >> 1, kqB = (tid & 1) * 8;

    float acc[4][8];
#pragma unroll
    for (int i = 0; i < 4; i++)
#pragma unroll
        for (int j = 0; j < 8; j++) acc[i][j] = 0.0f;

    const float* hrow = &g_cat[(size_t)((l-1)*BATCH + bm + rA) * KCAT];
    const float* wrow = &W_hh[(size_t)(bn + rB) * H];

    for (int k0 = ks*128; k0 < ks*128 + 128; k0 += 16) {
        __syncthreads();
        float4 av  = *(const float4*)&hrow[k0 + kqA];
        float4 bv0 = *(const float4*)&wrow[k0 + kqB];
        float4 bv1 = *(const float4*)&wrow[k0 + kqB + 4];
        As[kqA+0][rA] = av.x; As[kqA+1][rA] = av.y; As[kqA+2][rA] = av.z; As[kqA+3][rA] = av.w;
        Bs[kqB+0][rB] = bv0.x; Bs[kqB+1][rB] = bv0.y; Bs[kqB+2][rB] = bv0.z; Bs[kqB+3][rB] = bv0.w;
        Bs[kqB+4][rB] = bv1.x; Bs[kqB+5][rB] = bv1.y; Bs[kqB+6][rB] = bv1.z; Bs[kqB+7][rB] = bv1.w;
        __syncthreads();
#pragma unroll
        for (int kk = 0; kk < 16; kk++) {
            float4 a  = *(const float4*)&As[kk][ty*4];
            float4 b0 = *(const float4*)&Bs[kk][tx*4];
            float4 b1 = *(const float4*)&Bs[kk][64 + tx*4];
            float ra[4] = {a.x, a.y, a.z, a.w};
            float rbv[8] = {b0.x, b0.y, b0.z, b0.w, b1.x, b1.y, b1.z, b1.w};
#pragma unroll
            for (int i = 0; i < 4; i++)
#pragma unroll
                for (int j = 0; j < 8; j++) acc[i][j] += ra[i] * rbv[j];
        }
    }
#pragma unroll
    for (int i = 0; i < 4; i++) {
        int row = bm + ty*4 + i;
        *(float4*)&g_part[((size_t)ks*BATCH + row) * G4 + bn + tx*4] =
            make_float4(acc[i][0], acc[i][1], acc[i][2], acc[i][3]);
        *(float4*)&g_part[((size_t)ks*BATCH + row) * G4 + bn + 64 + tx*4] =
            make_float4(acc[i][4], acc[i][5], acc[i][6], acc[i][7]);
    }
}

// ---------------- LSTM step, phase 2: reduce K-splits + pointwise ----------------
__global__ void lstm_reduce(const float* __restrict__ b_hh, int l, int first) {
    const int idx = blockIdx.x * 256 + threadIdx.x;   // idx = b*512 + d
    const int d = idx & 511, b = idx >> 9;
    float g[4];
#pragma unroll
    for (int q = 0; q < 4; q++) {
        const int n = q*H + d;
        float v = g_xg[(size_t)(l*BATCH + b) * G4 + n] + b_hh[n];
        if (!first) {
#pragma unroll
            for (int s = 0; s < 4; s++) v += g_part[((size_t)s*BATCH + b) * G4 + n];
        }
        g[q] = v;
    }
    float ig = sigmoid_acc(g[0]);
    float fg = sigmoid_acc(g[1]);
    float gg = tanhf(g[2]);
    float og = sigmoid_acc(g[3]);
    float cp = first ? 0.0f : g_c[idx];
    float cn = fg*cp + ig*gg;
    g_c[idx] = cn;
    g_cat[(size_t)(l*BATCH + b) * KCAT + d] = og * tanhf(cn);
}

// ---------------- K4a: feat_att[l,b,n] ----------------
__global__ void featatt_kernel(const float* __restrict__ x_em,
                               const float* __restrict__ attw_w,
                               const float* __restrict__ attw_b) {
    __shared__ float sx[512][17];
    __shared__ float sh_hem[512];
    __shared__ float sh_w[512];
    __shared__ float red[16][17];
    const int tid = threadIdx.x;
    const int b  = blockIdx.y;
    const int n0 = blockIdx.x * 16;
#pragma unroll
    for (int i = 0; i < 32; i++) {
        int e = tid + i*256;
        int c = e >> 4, j = e & 15;
        sx[c][j] = x_em[((size_t)b*512 + c) * 256 + n0 + j];
    }
    sh_w[tid]     = attw_w[tid];
    sh_w[tid+256] = attw_w[tid+256];
    const float ab = attw_b[0];
    const int j  = tid % 16;
    const int cg = tid / 16;
    for (int l = 0; l < L; l++) {
        __syncthreads();
        sh_hem[tid]     = g_hem[(size_t)(l*BATCH + b) * H + tid];
        sh_hem[tid+256] = g_hem[(size_t)(l*BATCH + b) * H + tid + 256];
        __syncthreads();
        float acc = 0.0f;
#pragma unroll 8
        for (int i = 0; i < 32; i++) {
            int c = cg*32 + i;
            acc += tanh_approx(sx[c][j] + sh_hem[c]) * sh_w[c];
        }
        red[cg][j] = acc;
        __syncthreads();
        if (tid < 16) {
            float s = 0.0f;
#pragma unroll
            for (int i = 0; i < 16; i++) s += red[i][tid];
            g_fatt[(size_t)(l*BATCH + b) * HW + n0 + tid] = s + ab;
        }
    }
}

// ---------------- K4b: softmax + att reduction ----------------
__global__ void attred_kernel(const float* __restrict__ att_x_em) {
    __shared__ float s_alpha[L][HW];
    __shared__ float s_red[8];
    __shared__ float s_val;
    const int tid = threadIdx.x;
    const int b = blockIdx.x;
    const int lane = tid & 31, wid = tid >> 5;
    for (int l = 0; l < L; l++) {
        float v = g_fatt[(size_t)(l*BATCH + b) * HW + tid];
        float m = v;
#pragma unroll
        for (int o = 16; o > 0; o >>= 1) m = fmaxf(m, __shfl_xor_sync(~0u, m, o));
        if (lane == 0) s_red[wid] = m;
        __syncthreads();
        if (tid == 0) {
            float mm = s_red[0];
#pragma unroll
            for (int i = 1; i < 8; i++) mm = fmaxf(mm, s_red[i]);
            s_val = mm;
        }
        __syncthreads();
        float e = __expf(v - s_val);
        float s = e;
#pragma unroll
        for (int o = 16; o > 0; o >>= 1) s += __shfl_xor_sync(~0u, s, o);
        if (lane == 0) s_red[wid] = s;
        __syncthreads();
        if (tid == 0) {
            float ss = 0.0f;
#pragma unroll
            for (int i = 0; i < 8; i++) ss += s_red[i];
            s_val = ss;
        }
        __syncthreads();
        s_alpha[l][tid] = e / s_val;
        __syncthreads();
    }
    float acc[L][2];
#pragma unroll
    for (int l = 0; l < L; l++) { acc[l][0] = 0.0f; acc[l][1] = 0.0f; }
    const float* axb = att_x_em + (size_t)b * HW * H;
    for (int n = 0; n < HW; n++) {
        float2 ax = *(const float2*)&axb[(size_t)n * H + 2*tid];
#pragma unroll
        for (int l = 0; l < L; l++) {
            float a = s_alpha[l][n];
            acc[l][0] += a * ax.x;
            acc[l][1] += a * ax.y;
        }
    }
#pragma unroll
    for (int l = 0; l < L; l++) {
        size_t o = (size_t)(l*BATCH + b) * KCAT + 512 + 2*tid;
        *(float2*)&g_cat[o] = make_float2(acc[l][0], acc[l][1]);
    }
}

// ---------------- K6: row log-softmax over 7000 classes ----------------
__global__ void logsoftmax_kernel(float* __restrict__ out) {
    const int m = blockIdx.x;
    const int l = m / BATCH, b = m % BATCH;
    const int tid = threadIdx.x;
    const int lane = tid & 31, wid = tid >> 5;
    __shared__ float s_red[8];
    __shared__ float s_val;
    float vals[28];
    const float* row = g_logits + (size_t)m * NCLS;
#pragma unroll
    for (int i = 0; i < 28; i++) {
        int idx = tid + i*256;
        vals[i] = (idx < NCLS) ? row[idx] : -1e30f;
    }
    float mx = -1e30f;
#pragma unroll
    for (int i = 0; i < 28; i++) mx = fmaxf(mx, vals[i]);
#pragma unroll
    for (int o = 16; o > 0; o >>= 1) mx = fmaxf(mx, __shfl_xor_sync(~0u, mx, o));
    if (lane == 0) s_red[wid] = mx;
    __syncthreads();
    if (tid == 0) {
        float mm = s_red[0];
#pragma unroll
        for (int i = 1; i < 8; i++) mm = fmaxf(mm, s_red[i]);
        s_val = mm;
    }
    __syncthreads();
    const float mall = s_val;
    float sum = 0.0f;
#pragma unroll
    for (int i = 0; i < 28; i++) sum += __expf(vals[i] - mall);
#pragma unroll
    for (int o = 16; o > 0; o >>= 1) sum += __shfl_xor_sync(~0u, sum, o);
    if (lane == 0) s_red[wid] = sum;
    __syncthreads();
    if (tid == 0) {
        float ss = 0.0f;
#pragma unroll
        for (int i = 0; i < 8; i++) ss += s_red[i];
        s_val = ss;
    }
    __syncthreads();
    const float lse = mall + logf(s_val);
    float* orow = out + ((size_t)b * L + l) * NCLS;
#pragma unroll
    for (int i = 0; i < 28; i++) {
        int idx = tid + i*256;
        if (idx < NCLS) orow[idx] = vals[i] - lse;
    }
}

// ---------------- launch ----------------
extern "C" void kernel_launch(void* const* d_in, const int* in_sizes, int n_in,
                              void* d_out, int out_size) {
    const float* hidden_en = (const float*)d_in[0];
    const float* x_em      = (const float*)d_in[1];
    const float* att_x_em  = (const float*)d_in[2];
    const int*   target    = (const int*)  d_in[3];
    const float* embed_w = (const float*)d_in[6];
    const float* W_ih    = (const float*)d_in[7];
    const float* W_hh    = (const float*)d_in[8];
    const float* b_ih    = (const float*)d_in[9];
    const float* b_hh    = (const float*)d_in[10];
    const float* hem_w   = (const float*)d_in[11];
    const float* hem_b   = (const float*)d_in[12];
    const float* attw_w  = (const float*)d_in[13];
    const float* attw_b  = (const float*)d_in[14];
    const float* lin_w   = (const float*)d_in[15];
    const float* lin_b   = (const float*)d_in[16];
    float* out = (float*)d_out;

    void *p_xts, *p_xg, *p_cat, *p_hem, *p_logits;
    cudaGetSymbolAddress(&p_xts,    g_xts);
    cudaGetSymbolAddress(&p_xg,     g_xg);
    cudaGetSymbolAddress(&p_cat,    g_cat);
    cudaGetSymbolAddress(&p_hem,    g_hem);
    cudaGetSymbolAddress(&p_logits, g_logits);

    // K0: gather teacher-forced inputs
    gather_kernel<<<M5, 128>>>(hidden_en, embed_w, target);

    // K1: xg_all = xts @ W_ih^T + b_ih   [5120 x 2048], K=512
    sgemm2_nt_bias<<<dim3(G4/128, M5/256), 256>>>(
        (const float*)p_xts, HIDI, W_ih, HIDI, b_ih, (float*)p_xg, G4, G4, HIDI);

    // K2: sequential LSTM
    lstm_reduce<<<BATCH*H/256, 256>>>(b_hh, 0, 1);
    for (int l = 1; l < L; l++) {
        lstm_gemm_part<<<dim3(16, 2, 4), 256>>>(W_hh, l);
        lstm_reduce<<<BATCH*H/256, 256>>>(b_hh, l, 0);
    }

    // K3: hem = H_all @ hem_w^T + hem_b   [5120 x 512], K=512 (A = g_cat, lda=1024)
    sgemm2_nt_bias<<<dim3(H/128, M5/256), 256>>>(
        (const float*)p_cat, KCAT, hem_w, H, hem_b, (float*)p_hem, H, H, H);

    // K4a: feat_att
    featatt_kernel<<<dim3(16, BATCH), 256>>>(x_em, attw_w, attw_b);

    // K4b: softmax + att
    attred_kernel<<<BATCH, 256>>>(att_x_em);

    // K5: logits = [h, att] @ lin_w^T + lin_b   [5120 x 7000], K=1024
    sgemm2_nt_bias<<<dim3((NCLS+127)/128, M5/256), 256>>>(
        (const float*)p_cat, KCAT, lin_w, KCAT, lin_b, (float*)p_logits, NCLS, NCLS, KCAT);

    // K6: log-softmax + transpose to [B, L, NCLS]
    logsoftmax_kernel<<<M5, 256>>>(out);
}

// round 4
// speedup vs baseline: 2.3289x; 1.6803x over previous
#include <cuda_runtime.h>
#include <cuda_bf16.h>
#include <math.h>
#include <cstdint>

#define L      40
#define BATCH  128
#define HIDI   512
#define H      512
#define G4     2048
#define NCLS   7000
#define NPAD   7040
#define HW     256
#define M5     (L*BATCH)   /* 5120 */
#define KCAT   1024

// ---------------- scratch (static device globals: no allocation) ----------------
__device__ float g_xts[M5*HIDI];
__device__ float g_xg [M5*G4];
__device__ float g_cat[M5*KCAT];                 // cols 0..511 = h, 512..1023 = att
__device__ float g_hem[M5*H];
__device__ float g_fatt[M5*HW];
__device__ float g_c  [BATCH*H];
__device__ float g_part[8*BATCH*G4];             // LSTM k-split partials
__device__ float g_logits[(size_t)M5*NCLS];
__device__ __nv_bfloat16 g_catbf[(size_t)M5*KCAT];
__device__ __nv_bfloat16 g_linbf[(size_t)NPAD*KCAT];

__device__ __forceinline__ float tanh_approx(float x) {
    float y; asm("tanh.approx.f32 %0, %1;" : "=f"(y) : "f"(x)); return y;
}
__device__ __forceinline__ float sigmoid_acc(float x) { return 1.0f / (1.0f + expf(-x)); }

__device__ __forceinline__ uint32_t smem_u32(const void* p) {
    uint32_t a;
    asm("{ .reg .u64 t; cvta.to.shared.u64 t, %1; cvt.u32.u64 %0, t; }" : "=r"(a) : "l"(p));
    return a;
}

// ---------------- K0: gather teacher-forced inputs ----------------
__global__ void gather_kernel(const float* __restrict__ hidden_en,
                              const float* __restrict__ embed_w,
                              const int*   __restrict__ target) {
    const int m = blockIdx.x;
    const int l = m / BATCH, b = m % BATCH;
    const int k = threadIdx.x * 4;
    const float* src = (l == 0)
        ? (hidden_en + (size_t)b * HIDI)
        : (embed_w   + (size_t)target[b * L + (l - 1)] * HIDI);
    *(float4*)&g_xts[(size_t)m * HIDI + k] = *(const float4*)&src[k];
}

// ---------------- f32x2 GEMM (K1, K3) ----------------
__global__ void __launch_bounds__(256) sgemm2_nt_bias(
        const float* __restrict__ A, int lda,
        const float* __restrict__ B, int ldb,
        const float* __restrict__ bias,
        float* __restrict__ C, int ldc,
        int N, int K) {
    __shared__ float As[8][264];
    __shared__ float Bs[8][136];
    const int bm = blockIdx.y * 256;
    const int bn = blockIdx.x * 128;
    const int tid = threadIdx.x;
    const int tx = tid & 15, ty = tid >> 4;
    const int rA = tid >> 1, kqA = (tid & 1) * 4;
    const int rB = tid & 127, kqB = (tid >> 7) * 4;

    unsigned long long acc[64];
#pragma unroll
    for (int i = 0; i < 64; i++) acc[i] = 0ULL;

    float4 ra0, ra1, rb;
    ra0 = *(const float4*)&A[(size_t)(bm + rA      ) * lda + kqA];
    ra1 = *(const float4*)&A[(size_t)(bm + 128 + rA) * lda + kqA];
    {
        int br = bn + rB;
        rb = (br < N) ? *(const float4*)&B[(size_t)br * ldb + kqB] : make_float4(0.f,0.f,0.f,0.f);
    }
    for (int k0 = 0; k0 < K; k0 += 8) {
        __syncthreads();
        As[kqA+0][rA] = ra0.x; As[kqA+1][rA] = ra0.y; As[kqA+2][rA] = ra0.z; As[kqA+3][rA] = ra0.w;
        As[kqA+0][128+rA] = ra1.x; As[kqA+1][128+rA] = ra1.y; As[kqA+2][128+rA] = ra1.z; As[kqA+3][128+rA] = ra1.w;
        Bs[kqB+0][rB] = rb.x; Bs[kqB+1][rB] = rb.y; Bs[kqB+2][rB] = rb.z; Bs[kqB+3][rB] = rb.w;
        __syncthreads();
        if (k0 + 8 < K) {
            ra0 = *(const float4*)&A[(size_t)(bm + rA      ) * lda + k0 + 8 + kqA];
            ra1 = *(const float4*)&A[(size_t)(bm + 128 + rA) * lda + k0 + 8 + kqA];
            int br = bn + rB;
            rb = (br < N) ? *(const float4*)&B[(size_t)br * ldb + k0 + 8 + kqB] : make_float4(0.f,0.f,0.f,0.f);
        }
#pragma unroll
        for (int kk = 0; kk < 8; kk++) {
            ulonglong2 a0 = *(const ulonglong2*)&As[kk][ty*16 + 0];
            ulonglong2 a1 = *(const ulonglong2*)&As[kk][ty*16 + 4];
            ulonglong2 a2 = *(const ulonglong2*)&As[kk][ty*16 + 8];
            ulonglong2 a3 = *(const ulonglong2*)&As[kk][ty*16 + 12];
            float4 b0 = *(const float4*)&Bs[kk][tx*4];
            float4 b1 = *(const float4*)&Bs[kk][64 + tx*4];
            unsigned long long ap[8] = {a0.x, a0.y, a1.x, a1.y, a2.x, a2.y, a3.x, a3.y};
            float bf[8] = {b0.x, b0.y, b0.z, b0.w, b1.x, b1.y, b1.z, b1.w};
#pragma unroll
            for (int j = 0; j < 8; j++) {
                unsigned long long bd;
                asm("mov.b64 %0, {%1, %1};" : "=l"(bd) : "f"(bf[j]));
#pragma unroll
                for (int ip = 0; ip < 8; ip++)
                    asm("fma.rn.f32x2 %0, %1, %2, %0;" : "+l"(acc[ip*8+j]) : "l"(ap[ip]), "l"(bd));
            }
        }
    }
    const int c0 = bn + tx*4;
    const int c1 = bn + 64 + tx*4;
    float4 bb0 = make_float4(0.f,0.f,0.f,0.f), bb1 = bb0;
    if (c0 < N) bb0 = *(const float4*)&bias[c0];
    if (c1 < N) bb1 = *(const float4*)&bias[c1];
#pragma unroll
    for (int ip = 0; ip < 8; ip++) {
        const int r = bm + ty*16 + ip*2;
        float2 p[8];
#pragma unroll
        for (int j = 0; j < 8; j++)
            asm("mov.b64 {%0, %1}, %2;" : "=f"(p[j].x), "=f"(p[j].y) : "l"(acc[ip*8+j]));
        if (c0 < N) {
            *(float4*)&C[(size_t)r*ldc + c0]     = make_float4(p[0].x+bb0.x, p[1].x+bb0.y, p[2].x+bb0.z, p[3].x+bb0.w);
            *(float4*)&C[(size_t)(r+1)*ldc + c0] = make_float4(p[0].y+bb0.x, p[1].y+bb0.y, p[2].y+bb0.z, p[3].y+bb0.w);
        }
        if (c1 < N) {
            *(float4*)&C[(size_t)r*ldc + c1]     = make_float4(p[4].x+bb1.x, p[5].x+bb1.y, p[6].x+bb1.z, p[7].x+bb1.w);
            *(float4*)&C[(size_t)(r+1)*ldc + c1] = make_float4(p[4].y+bb1.x, p[5].y+bb1.y, p[6].y+bb1.z, p[7].y+bb1.w);
        }
    }
}

// ---------------- LSTM phase 1: K-split partial GEMM (8 splits of 64) ----------------
__global__ void __launch_bounds__(256) lstm_gemm_part(const float* __restrict__ W_hh, int l) {
    __shared__ float As[16][68];
    __shared__ float Bs[16][136];
    const int tid = threadIdx.x;
    const int bn = blockIdx.x * 128;
    const int bm = blockIdx.y * 64;
    const int ks = blockIdx.z;
    const int tx = tid & 15, ty = tid >> 4;
    const int rA = tid >> 2, kqA = (tid & 3) * 4;
    const int rB = tid >> 1, kqB = (tid & 1) * 8;

    float acc[4][8];
#pragma unroll
    for (int i = 0; i < 4; i++)
#pragma unroll
        for (int j = 0; j < 8; j++) acc[i][j] = 0.0f;

    const float* hrow = &g_cat[(size_t)((l-1)*BATCH + bm + rA) * KCAT];
    const float* wrow = &W_hh[(size_t)(bn + rB) * H];

    for (int k0 = ks*64; k0 < ks*64 + 64; k0 += 16) {
        __syncthreads();
        float4 av  = *(const float4*)&hrow[k0 + kqA];
        float4 bv0 = *(const float4*)&wrow[k0 + kqB];
        float4 bv1 = *(const float4*)&wrow[k0 + kqB + 4];
        As[kqA+0][rA] = av.x; As[kqA+1][rA] = av.y; As[kqA+2][rA] = av.z; As[kqA+3][rA] = av.w;
        Bs[kqB+0][rB] = bv0.x; Bs[kqB+1][rB] = bv0.y; Bs[kqB+2][rB] = bv0.z; Bs[kqB+3][rB] = bv0.w;
        Bs[kqB+4][rB] = bv1.x; Bs[kqB+5][rB] = bv1.y; Bs[kqB+6][rB] = bv1.z; Bs[kqB+7][rB] = bv1.w;
        __syncthreads();
#pragma unroll
        for (int kk = 0; kk < 16; kk++) {
            float4 a  = *(const float4*)&As[kk][ty*4];
            float4 b0 = *(const float4*)&Bs[kk][tx*4];
            float4 b1 = *(const float4*)&Bs[kk][64 + tx*4];
            float ra[4] = {a.x, a.y, a.z, a.w};
            float rbv[8] = {b0.x, b0.y, b0.z, b0.w, b1.x, b1.y, b1.z, b1.w};
#pragma unroll
            for (int i = 0; i < 4; i++)
#pragma unroll
                for (int j = 0; j < 8; j++) acc[i][j] += ra[i] * rbv[j];
        }
    }
#pragma unroll
    for (int i = 0; i < 4; i++) {
        int row = bm + ty*4 + i;
        *(float4*)&g_part[((size_t)ks*BATCH + row) * G4 + bn + tx*4] =
            make_float4(acc[i][0], acc[i][1], acc[i][2], acc[i][3]);
        *(float4*)&g_part[((size_t)ks*BATCH + row) * G4 + bn + 64 + tx*4] =
            make_float4(acc[i][4], acc[i][5], acc[i][6], acc[i][7]);
    }
}

// ---------------- LSTM phase 2: reduce + pointwise ----------------
__global__ void lstm_reduce(const float* __restrict__ b_hh, int l, int first) {
    const int idx = blockIdx.x * 256 + threadIdx.x;
    const int d = idx & 511, b = idx >> 9;
    float g[4];
#pragma unroll
    for (int q = 0; q < 4; q++) {
        const int n = q*H + d;
        float v = g_xg[(size_t)(l*BATCH + b) * G4 + n] + b_hh[n];
        if (!first) {
#pragma unroll
            for (int s = 0; s < 8; s++) v += g_part[((size_t)s*BATCH + b) * G4 + n];
        }
        g[q] = v;
    }
    float ig = sigmoid_acc(g[0]);
    float fg = sigmoid_acc(g[1]);
    float gg = tanhf(g[2]);
    float og = sigmoid_acc(g[3]);
    float cp = first ? 0.0f : g_c[idx];
    float cn = fg*cp + ig*gg;
    g_c[idx] = cn;
    g_cat[(size_t)(l*BATCH + b) * KCAT + d] = og * tanhf(cn);
}

// ---------------- K4a ----------------
__global__ void featatt_kernel(const float* __restrict__ x_em,
                               const float* __restrict__ attw_w,
                               const float* __restrict__ attw_b) {
    __shared__ float sx[512][17];
    __shared__ float sh_hem[512];
    __shared__ float sh_w[512];
    __shared__ float red[16][17];
    const int tid = threadIdx.x;
    const int b  = blockIdx.y;
    const int n0 = blockIdx.x * 16;
#pragma unroll
    for (int i = 0; i < 32; i++) {
        int e = tid + i*256;
        int c = e >> 4, j = e & 15;
        sx[c][j] = x_em[((size_t)b*512 + c) * 256 + n0 + j];
    }
    sh_w[tid]     = attw_w[tid];
    sh_w[tid+256] = attw_w[tid+256];
    const float ab = attw_b[0];
    const int j  = tid % 16;
    const int cg = tid / 16;
    for (int l = 0; l < L; l++) {
        __syncthreads();
        sh_hem[tid]     = g_hem[(size_t)(l*BATCH + b) * H + tid];
        sh_hem[tid+256] = g_hem[(size_t)(l*BATCH + b) * H + tid + 256];
        __syncthreads();
        float acc = 0.0f;
#pragma unroll 8
        for (int i = 0; i < 32; i++) {
            int c = cg*32 + i;
            acc += tanh_approx(sx[c][j] + sh_hem[c]) * sh_w[c];
        }
        red[cg][j] = acc;
        __syncthreads();
        if (tid < 16) {
            float s = 0.0f;
#pragma unroll
            for (int i = 0; i < 16; i++) s += red[i][tid];
            g_fatt[(size_t)(l*BATCH + b) * HW + n0 + tid] = s + ab;
        }
    }
}

// ---------------- K4b ----------------
__global__ void attred_kernel(const float* __restrict__ att_x_em) {
    __shared__ float s_alpha[L][HW];
    __shared__ float s_red[8];
    __shared__ float s_val;
    const int tid = threadIdx.x;
    const int b = blockIdx.x;
    const int lane = tid & 31, wid = tid >> 5;
    for (int l = 0; l < L; l++) {
        float v = g_fatt[(size_t)(l*BATCH + b) * HW + tid];
        float m = v;
#pragma unroll
        for (int o = 16; o > 0; o >>= 1) m = fmaxf(m, __shfl_xor_sync(~0u, m, o));
        if (lane == 0) s_red[wid] = m;
        __syncthreads();
        if (tid == 0) {
            float mm = s_red[0];
#pragma unroll
            for (int i = 1; i < 8; i++) mm = fmaxf(mm, s_red[i]);
            s_val = mm;
        }
        __syncthreads();
        float e = __expf(v - s_val);
        float s = e;
#pragma unroll
        for (int o = 16; o > 0; o >>= 1) s += __shfl_xor_sync(~0u, s, o);
        if (lane == 0) s_red[wid] = s;
        __syncthreads();
        if (tid == 0) {
            float ss = 0.0f;
#pragma unroll
            for (int i = 0; i < 8; i++) ss += s_red[i];
            s_val = ss;
        }
        __syncthreads();
        s_alpha[l][tid] = e / s_val;
        __syncthreads();
    }
    float acc[L][2];
#pragma unroll
    for (int l = 0; l < L; l++) { acc[l][0] = 0.0f; acc[l][1] = 0.0f; }
    const float* axb = att_x_em + (size_t)b * HW * H;
    for (int n = 0; n < HW; n++) {
        float2 ax = *(const float2*)&axb[(size_t)n * H + 2*tid];
#pragma unroll
        for (int l = 0; l < L; l++) {
            float a = s_alpha[l][n];
            acc[l][0] += a * ax.x;
            acc[l][1] += a * ax.y;
        }
    }
#pragma unroll
    for (int l = 0; l < L; l++) {
        size_t o = (size_t)(l*BATCH + b) * KCAT + 512 + 2*tid;
        *(float2*)&g_cat[o] = make_float2(acc[l][0], acc[l][1]);
    }
}

// ---------------- conversions to bf16 ----------------
__global__ void conv_cat_bf(void) {
    const size_t i = ((size_t)blockIdx.x * 256 + threadIdx.x) * 4;
    float4 v = *(const float4*)&g_cat[i];
    __nv_bfloat162 a = __floats2bfloat162_rn(v.x, v.y);
    __nv_bfloat162 b = __floats2bfloat162_rn(v.z, v.w);
    *(uint2*)&g_catbf[i] = make_uint2(*(uint32_t*)&a, *(uint32_t*)&b);
}
__global__ void conv_lin_bf(const float* __restrict__ lin_w) {
    const size_t i = ((size_t)blockIdx.x * 256 + threadIdx.x) * 4;
    const size_t row = i / KCAT;
    float4 v = (row < NCLS) ? *(const float4*)&lin_w[i] : make_float4(0.f,0.f,0.f,0.f);
    __nv_bfloat162 a = __floats2bfloat162_rn(v.x, v.y);
    __nv_bfloat162 b = __floats2bfloat162_rn(v.z, v.w);
    *(uint2*)&g_linbf[i] = make_uint2(*(uint32_t*)&a, *(uint32_t*)&b);
}

// ---------------- K5: bf16 mma.sync GEMM  logits = cat_bf @ linbf^T + bias ----------------
// CTA 128x128, K-chunk 32, double-buffered SMEM with 80B-padded rows
// (row stride 80B => (r*5)%8 distinct 16B sub-banks => conflict-free ldmatrix).
// 8 warps in 2x4; warp tile 64x32 via 4x4 m16n8k16 atoms, fp32 accum.
#define K5_LDS   40          /* bf16 elements per padded row (32 data + 8 pad) */
#define K5_ROWB  80          /* bytes per row */
#define K5_BUFB  (128*K5_ROWB)
#define K5_NCH   (KCAT/32)

__device__ __forceinline__ void ldsm_x4(uint32_t* r, uint32_t addr) {
    asm volatile("ldmatrix.sync.aligned.m8n8.x4.shared.b16 {%0,%1,%2,%3}, [%4];"
                 : "=r"(r[0]), "=r"(r[1]), "=r"(r[2]), "=r"(r[3]) : "r"(addr));
}
__device__ __forceinline__ void mma16816(float* c, const uint32_t* a, uint32_t b0, uint32_t b1) {
    asm volatile("mma.sync.aligned.m16n8k16.row.col.f32.bf16.bf16.f32 "
                 "{%0,%1,%2,%3}, {%4,%5,%6,%7}, {%8,%9}, {%0,%1,%2,%3};"
                 : "+f"(c[0]), "+f"(c[1]), "+f"(c[2]), "+f"(c[3])
                 : "r"(a[0]), "r"(a[1]), "r"(a[2]), "r"(a[3]), "r"(b0), "r"(b1));
}

__global__ void __launch_bounds__(256) k5_hmma_kernel(const float* __restrict__ bias) {
    __shared__ __nv_bfloat16 sA[2][128][K5_LDS];
    __shared__ __nv_bfloat16 sB[2][128][K5_LDS];
    const int tid  = threadIdx.x;
    const int w    = tid >> 5, lane = tid & 31;
    const int wm   = w >> 2, wn = w & 3;           // 2 x 4 warp grid
    const int bm   = blockIdx.y * 128;
    const int bn   = blockIdx.x * 128;

    const uint32_t uA = smem_u32(&sA[0][0][0]);
    const uint32_t uB = smem_u32(&sB[0][0][0]);

    // global load mapping: 512 16B-chunks per matrix per k-chunk, 2 per thread
    const int gr0 = tid >> 1;                       // rows 0..127 (chunks 0,1 of row)
    const int gs0 = tid & 1;
    const int gr1 = tid >> 1;                       // same row, chunks 2,3
    const int gs1 = 2 + (tid & 1);
    const __nv_bfloat16* arow = g_catbf + (size_t)(bm + gr0) * KCAT;
    const __nv_bfloat16* brow = g_linbf + (size_t)(bn + gr0) * KCAT;

    float acc[4][4][4];
#pragma unroll
    for (int i = 0; i < 4; i++)
#pragma unroll
        for (int j = 0; j < 4; j++)
#pragma unroll
            for (int q = 0; q < 4; q++) acc[i][j][q] = 0.0f;

    uint4 ra[2], rb[2];
    // preload chunk 0
    ra[0] = *(const uint4*)(arow + gs0*8);
    ra[1] = *(const uint4*)(arow + gs1*8);
    rb[0] = *(const uint4*)(brow + gs0*8);
    rb[1] = *(const uint4*)(brow + gs1*8);
    *(uint4*)((char*)&sA[0][0][0] + gr0*K5_ROWB + gs0*16) = ra[0];
    *(uint4*)((char*)&sA[0][0][0] + gr1*K5_ROWB + gs1*16) = ra[1];
    *(uint4*)((char*)&sB[0][0][0] + gr0*K5_ROWB + gs0*16) = rb[0];
    *(uint4*)((char*)&sB[0][0][0] + gr1*K5_ROWB + gs1*16) = rb[1];

    // ldmatrix lane address components (within a buffer)
    const uint32_t aoff = (uint32_t)(wm*64 + (lane & 15)) * K5_ROWB + (uint32_t)(lane >> 4) * 16;
    const uint32_t boff = (uint32_t)(wn*32 + (lane & 15)) * K5_ROWB + (uint32_t)(lane >> 4) * 16;

    for (int c = 0; c < K5_NCH; c++) {
        __syncthreads();                         // smem[c&1] ready for all
        if (c + 1 < K5_NCH) {
            const int k0 = (c + 1) * 32;
            ra[0] = *(const uint4*)(arow + k0 + gs0*8);
            ra[1] = *(const uint4*)(arow + k0 + gs1*8);
            rb[0] = *(const uint4*)(brow + k0 + gs0*8);
            rb[1] = *(const uint4*)(brow + k0 + gs1*8);
        }
        const uint32_t bufA = uA + (c & 1) * K5_BUFB;
        const uint32_t bufB = uB + (c & 1) * K5_BUFB;
#pragma unroll
        for (int ka = 0; ka < 2; ka++) {
            uint32_t af[4][4];
            uint32_t bf[2][4];
#pragma unroll
            for (int ma = 0; ma < 4; ma++)
                ldsm_x4(af[ma], bufA + aoff + ma*16*K5_ROWB + ka*32);
#pragma unroll
            for (int ng = 0; ng < 2; ng++)
                ldsm_x4(bf[ng], bufB + boff + ng*16*K5_ROWB + ka*32);
            // bf[ng] regs: r0=(n-atom ng*2+0, k0-7), r1=(n-atom ng*2+1, k0-7), r2/r3 = k8-15
#pragma unroll
            for (int ma = 0; ma < 4; ma++)
#pragma unroll
                for (int ng = 0; ng < 2; ng++) {
                    mma16816(acc[ma][ng*2+0], af[ma], bf[ng][0], bf[ng][2]);
                    mma16816(acc[ma][ng*2+1], af[ma], bf[ng][1], bf[ng][3]);
                }
        }
        if (c + 1 < K5_NCH) {
            __syncthreads();                     // everyone done reading buffer (c+1)&1
            char* dA = (char*)&sA[(c+1)&1][0][0];
            char* dB = (char*)&sB[(c+1)&1][0][0];
            *(uint4*)(dA + gr0*K5_ROWB + gs0*16) = ra[0];
            *(uint4*)(dA + gr1*K5_ROWB + gs1*16) = ra[1];
            *(uint4*)(dB + gr0*K5_ROWB + gs0*16) = rb[0];
            *(uint4*)(dB + gr1*K5_ROWB + gs1*16) = rb[1];
        }
    }

    // epilogue: lane (g = lane>>2, t = lane&3): c0,c1 -> row g cols 2t,2t+1; c2,c3 -> row g+8
    const int g = lane >> 2, t = lane & 3;
#pragma unroll
    for (int ma = 0; ma < 4; ma++) {
        const int r0 = bm + wm*64 + ma*16 + g;
#pragma unroll
        for (int na = 0; na < 4; na++) {
            const int col = bn + wn*32 + na*8 + t*2;
            if (col + 1 < NCLS) {
                const float2 bv = *(const float2*)&bias[col];
                *(float2*)&g_logits[(size_t)r0 * NCLS + col] =
                    make_float2(acc[ma][na][0] + bv.x, acc[ma][na][1] + bv.y);
                *(float2*)&g_logits[(size_t)(r0 + 8) * NCLS + col] =
                    make_float2(acc[ma][na][2] + bv.x, acc[ma][na][3] + bv.y);
            }
        }
    }
}

// ---------------- K6: row log-softmax ----------------
__global__ void logsoftmax_kernel(float* __restrict__ out) {
    const int m = blockIdx.x;
    const int l = m / BATCH, b = m % BATCH;
    const int tid = threadIdx.x;
    const int lane = tid & 31, wid = tid >> 5;
    __shared__ float s_red[8];
    __shared__ float s_val;
    float vals[28];
    const float* row = g_logits + (size_t)m * NCLS;
#pragma unroll
    for (int i = 0; i < 28; i++) {
        int idx = tid + i*256;
        vals[i] = (idx < NCLS) ? row[idx] : -1e30f;
    }
    float mx = -1e30f;
#pragma unroll
    for (int i = 0; i < 28; i++) mx = fmaxf(mx, vals[i]);
#pragma unroll
    for (int o = 16; o > 0; o >>= 1) mx = fmaxf(mx, __shfl_xor_sync(~0u, mx, o));
    if (lane == 0) s_red[wid] = mx;
    __syncthreads();
    if (tid == 0) {
        float mm = s_red[0];
#pragma unroll
        for (int i = 1; i < 8; i++) mm = fmaxf(mm, s_red[i]);
        s_val = mm;
    }
    __syncthreads();
    const float mall = s_val;
    float sum = 0.0f;
#pragma unroll
    for (int i = 0; i < 28; i++) sum += __expf(vals[i] - mall);
#pragma unroll
    for (int o = 16; o > 0; o >>= 1) sum += __shfl_xor_sync(~0u, sum, o);
    if (lane == 0) s_red[wid] = sum;
    __syncthreads();
    if (tid == 0) {
        float ss = 0.0f;
#pragma unroll
        for (int i = 0; i < 8; i++) ss += s_red[i];
        s_val = ss;
    }
    __syncthreads();
    const float lse = mall + logf(s_val);
    float* orow = out + ((size_t)b * L + l) * NCLS;
#pragma unroll
    for (int i = 0; i < 28; i++) {
        int idx = tid + i*256;
        if (idx < NCLS) orow[idx] = vals[i] - lse;
    }
}

// ---------------- launch ----------------
extern "C" void kernel_launch(void* const* d_in, const int* in_sizes, int n_in,
                              void* d_out, int out_size) {
    const float* hidden_en = (const float*)d_in[0];
    const float* x_em      = (const float*)d_in[1];
    const float* att_x_em  = (const float*)d_in[2];
    const int*   target    = (const int*)  d_in[3];
    const float* embed_w = (const float*)d_in[6];
    const float* W_ih    = (const float*)d_in[7];
    const float* W_hh    = (const float*)d_in[8];
    const float* b_ih    = (const float*)d_in[9];
    const float* b_hh    = (const float*)d_in[10];
    const float* hem_w   = (const float*)d_in[11];
    const float* hem_b   = (const float*)d_in[12];
    const float* attw_w  = (const float*)d_in[13];
    const float* attw_b  = (const float*)d_in[14];
    const float* lin_w   = (const float*)d_in[15];
    const float* lin_b   = (const float*)d_in[16];
    float* out = (float*)d_out;

    void *p_xts, *p_xg, *p_cat, *p_hem;
    cudaGetSymbolAddress(&p_xts, g_xts);
    cudaGetSymbolAddress(&p_xg,  g_xg);
    cudaGetSymbolAddress(&p_cat, g_cat);
    cudaGetSymbolAddress(&p_hem, g_hem);

    // K0
    gather_kernel<<<M5, 128>>>(hidden_en, embed_w, target);

    // lin_w -> bf16 (independent; do it early)
    conv_lin_bf<<<(NPAD*KCAT/4)/256, 256>>>(lin_w);

    // K1
    sgemm2_nt_bias<<<dim3(G4/128, M5/256), 256>>>(
        (const float*)p_xts, HIDI, W_ih, HIDI, b_ih, (float*)p_xg, G4, G4, HIDI);

    // K2
    lstm_reduce<<<BATCH*H/256, 256>>>(b_hh, 0, 1);
    for (int l = 1; l < L; l++) {
        lstm_gemm_part<<<dim3(16, 2, 8), 256>>>(W_hh, l);
        lstm_reduce<<<BATCH*H/256, 256>>>(b_hh, l, 0);
    }

    // K3
    sgemm2_nt_bias<<<dim3(H/128, M5/256), 256>>>(
        (const float*)p_cat, KCAT, hem_w, H, hem_b, (float*)p_hem, H, H, H);

    // K4a, K4b
    featatt_kernel<<<dim3(16, BATCH), 256>>>(x_em, attw_w, attw_b);
    attred_kernel<<<BATCH, 256>>>(att_x_em);

    // cat -> bf16
    conv_cat_bf<<<((size_t)M5*KCAT/4)/256, 256>>>();

    // K5: bf16 tensor-core GEMM (mma.sync — compiles under compute_103)
    k5_hmma_kernel<<<dim3(NPAD/128, M5/128), 256>>>(lin_b);

    // K6
    logsoftmax_kernel<<<M5, 256>>>(out);
}

// round 5
// speedup vs baseline: 2.7278x; 1.1713x over previous
#include <cuda_runtime.h>
#include <cuda_bf16.h>
#include <math.h>
#include <cstdint>

#define L      40
#define BATCH  128
#define HIDI   512
#define H      512
#define G4     2048
#define NCLS   7000
#define NPAD   7040
#define HW     256
#define M5     (L*BATCH)   /* 5120 */
#define KCAT   1024

// ---------------- scratch (static device globals: no allocation) ----------------
__device__ float g_xts[M5*HIDI];
__device__ float g_xg [M5*G4];
__device__ float g_cat[M5*KCAT];                 // cols 0..511 = h (fp32, for K3)
__device__ float g_hem[M5*H];
__device__ float g_fatt[M5*HW];
__device__ float g_c  [BATCH*H];
__device__ float g_part[8*BATCH*G4];             // LSTM k-split partials
__device__ float g_logits[(size_t)M5*NCLS];
__device__ __nv_bfloat16 g_catbf[(size_t)M5*KCAT];   // h | att, bf16 (K5 input)
__device__ __nv_bfloat16 g_linbf[(size_t)NPAD*KCAT];
__device__ __nv_bfloat16 g_whhbf[G4*H];
__device__ unsigned int g_bar_cnt;               // zero-init; self-restoring
__device__ volatile unsigned int g_bar_gen;

__device__ __forceinline__ float tanh_approx(float x) {
    float y; asm("tanh.approx.f32 %0, %1;" : "=f"(y) : "f"(x)); return y;
}
__device__ __forceinline__ float sigmoid_acc(float x) { return 1.0f / (1.0f + expf(-x)); }

__device__ __forceinline__ uint32_t smem_u32(const void* p) {
    uint32_t a;
    asm("{ .reg .u64 t; cvta.to.shared.u64 t, %1; cvt.u32.u64 %0, t; }" : "=r"(a) : "l"(p));
    return a;
}
__device__ __forceinline__ void ldsm_x4(uint32_t* r, uint32_t addr) {
    asm volatile("ldmatrix.sync.aligned.m8n8.x4.shared.b16 {%0,%1,%2,%3}, [%4];"
                 : "=r"(r[0]), "=r"(r[1]), "=r"(r[2]), "=r"(r[3]) : "r"(addr));
}
__device__ __forceinline__ void mma16816(float* c, const uint32_t* a, uint32_t b0, uint32_t b1) {
    asm volatile("mma.sync.aligned.m16n8k16.row.col.f32.bf16.bf16.f32 "
                 "{%0,%1,%2,%3}, {%4,%5,%6,%7}, {%8,%9}, {%0,%1,%2,%3};"
                 : "+f"(c[0]), "+f"(c[1]), "+f"(c[2]), "+f"(c[3])
                 : "r"(a[0]), "r"(a[1]), "r"(a[2]), "r"(a[3]), "r"(b0), "r"(b1));
}

// grid-wide software barrier (all 128 CTAs co-resident; count self-resets)
__device__ __forceinline__ void gbar(int nblk) {
    __syncthreads();
    if (threadIdx.x == 0) {
        __threadfence();
        unsigned int gen = g_bar_gen;
        if (atomicAdd(&g_bar_cnt, 1u) == (unsigned)(nblk - 1)) {
            g_bar_cnt = 0;
            __threadfence();
            g_bar_gen = gen + 1;
        } else {
            while (g_bar_gen == gen) { __nanosleep(32); }
        }
        __threadfence();
    }
    __syncthreads();
}

// ---------------- K0: gather teacher-forced inputs ----------------
__global__ void gather_kernel(const float* __restrict__ hidden_en,
                              const float* __restrict__ embed_w,
                              const int*   __restrict__ target) {
    const int m = blockIdx.x;
    const int l = m / BATCH, b = m % BATCH;
    const int k = threadIdx.x * 4;
    const float* src = (l == 0)
        ? (hidden_en + (size_t)b * HIDI)
        : (embed_w   + (size_t)target[b * L + (l - 1)] * HIDI);
    *(float4*)&g_xts[(size_t)m * HIDI + k] = *(const float4*)&src[k];
}

// ---------------- f32x2 GEMM (K1, K3) ----------------
__global__ void __launch_bounds__(256) sgemm2_nt_bias(
        const float* __restrict__ A, int lda,
        const float* __restrict__ B, int ldb,
        const float* __restrict__ bias,
        float* __restrict__ C, int ldc,
        int N, int K) {
    __shared__ float As[8][264];
    __shared__ float Bs[8][136];
    const int bm = blockIdx.y * 256;
    const int bn = blockIdx.x * 128;
    const int tid = threadIdx.x;
    const int tx = tid & 15, ty = tid >> 4;
    const int rA = tid >> 1, kqA = (tid & 1) * 4;
    const int rB = tid & 127, kqB = (tid >> 7) * 4;

    unsigned long long acc[64];
#pragma unroll
    for (int i = 0; i < 64; i++) acc[i] = 0ULL;

    float4 ra0, ra1, rb;
    ra0 = *(const float4*)&A[(size_t)(bm + rA      ) * lda + kqA];
    ra1 = *(const float4*)&A[(size_t)(bm + 128 + rA) * lda + kqA];
    {
        int br = bn + rB;
        rb = (br < N) ? *(const float4*)&B[(size_t)br * ldb + kqB] : make_float4(0.f,0.f,0.f,0.f);
    }
    for (int k0 = 0; k0 < K; k0 += 8) {
        __syncthreads();
        As[kqA+0][rA] = ra0.x; As[kqA+1][rA] = ra0.y; As[kqA+2][rA] = ra0.z; As[kqA+3][rA] = ra0.w;
        As[kqA+0][128+rA] = ra1.x; As[kqA+1][128+rA] = ra1.y; As[kqA+2][128+rA] = ra1.z; As[kqA+3][128+rA] = ra1.w;
        Bs[kqB+0][rB] = rb.x; Bs[kqB+1][rB] = rb.y; Bs[kqB+2][rB] = rb.z; Bs[kqB+3][rB] = rb.w;
        __syncthreads();
        if (k0 + 8 < K) {
            ra0 = *(const float4*)&A[(size_t)(bm + rA      ) * lda + k0 + 8 + kqA];
            ra1 = *(const float4*)&A[(size_t)(bm + 128 + rA) * lda + k0 + 8 + kqA];
            int br = bn + rB;
            rb = (br < N) ? *(const float4*)&B[(size_t)br * ldb + k0 + 8 + kqB] : make_float4(0.f,0.f,0.f,0.f);
        }
#pragma unroll
        for (int kk = 0; kk < 8; kk++) {
            ulonglong2 a0 = *(const ulonglong2*)&As[kk][ty*16 + 0];
            ulonglong2 a1 = *(const ulonglong2*)&As[kk][ty*16 + 4];
            ulonglong2 a2 = *(const ulonglong2*)&As[kk][ty*16 + 8];
            ulonglong2 a3 = *(const ulonglong2*)&As[kk][ty*16 + 12];
            float4 b0 = *(const float4*)&Bs[kk][tx*4];
            float4 b1 = *(const float4*)&Bs[kk][64 + tx*4];
            unsigned long long ap[8] = {a0.x, a0.y, a1.x, a1.y, a2.x, a2.y, a3.x, a3.y};
            float bf[8] = {b0.x, b0.y, b0.z, b0.w, b1.x, b1.y, b1.z, b1.w};
#pragma unroll
            for (int j = 0; j < 8; j++) {
                unsigned long long bd;
                asm("mov.b64 %0, {%1, %1};" : "=l"(bd) : "f"(bf[j]));
#pragma unroll
                for (int ip = 0; ip < 8; ip++)
                    asm("fma.rn.f32x2 %0, %1, %2, %0;" : "+l"(acc[ip*8+j]) : "l"(ap[ip]), "l"(bd));
            }
        }
    }
    const int c0 = bn + tx*4;
    const int c1 = bn + 64 + tx*4;
    float4 bb0 = make_float4(0.f,0.f,0.f,0.f), bb1 = bb0;
    if (c0 < N) bb0 = *(const float4*)&bias[c0];
    if (c1 < N) bb1 = *(const float4*)&bias[c1];
#pragma unroll
    for (int ip = 0; ip < 8; ip++) {
        const int r = bm + ty*16 + ip*2;
        float2 p[8];
#pragma unroll
        for (int j = 0; j < 8; j++)
            asm("mov.b64 {%0, %1}, %2;" : "=f"(p[j].x), "=f"(p[j].y) : "l"(acc[ip*8+j]));
        if (c0 < N) {
            *(float4*)&C[(size_t)r*ldc + c0]     = make_float4(p[0].x+bb0.x, p[1].x+bb0.y, p[2].x+bb0.z, p[3].x+bb0.w);
            *(float4*)&C[(size_t)(r+1)*ldc + c0] = make_float4(p[0].y+bb0.x, p[1].y+bb0.y, p[2].y+bb0.z, p[3].y+bb0.w);
        }
        if (c1 < N) {
            *(float4*)&C[(size_t)r*ldc + c1]     = make_float4(p[4].x+bb1.x, p[5].x+bb1.y, p[6].x+bb1.z, p[7].x+bb1.w);
            *(float4*)&C[(size_t)(r+1)*ldc + c1] = make_float4(p[4].y+bb1.x, p[5].y+bb1.y, p[6].y+bb1.z, p[7].y+bb1.w);
        }
    }
}

// ---------------- persistent LSTM: all 40 steps, one kernel ----------------
// 128 CTAs x 256 thr. CTA (bn = bid&31 -> 64 n-cols, ks = bid>>5 -> 128 k-cols).
// W_hh slice resident in SMEM (bf16). Per step: HMMA partial GEMM -> gbar ->
// distributed reduce+pointwise (writes h fp32 + bf16) -> gbar.
#define LP_NBLK 128
#define LP_ROWE 136            /* bf16 elems per padded smem row (128 + 8) */
#define LP_ROWB 272            /* bytes */

__global__ void __launch_bounds__(256) lstm_persist(const float* __restrict__ b_hh) {
    extern __shared__ __nv_bfloat16 sm[];
    __nv_bfloat16* sA = sm;                    // 128 x LP_ROWE (h tile)
    __nv_bfloat16* sB = sm + 128*LP_ROWE;      // 64 x LP_ROWE (W_hh slice)
    const int tid = threadIdx.x;
    const int w = tid >> 5, lane = tid & 31;
    const int wm = w >> 2, wn = w & 3;         // 2 x 4 warps; warp tile 64m x 16n
    const int bid = blockIdx.x;
    const int bn = (bid & 31) * 64;
    const int ks = bid >> 5;
    const uint32_t uA = smem_u32(sA), uB = smem_u32(sB);
    const int g = lane >> 2, t4 = lane & 3;

    // W_hh slice load (once): rows bn..bn+63, cols ks*128..+128
    for (int i = tid; i < 64*16; i += 256) {
        int r = i >> 4, cc = i & 15;
        *(uint4*)((char*)sB + r*LP_ROWB + cc*16) =
            *(const uint4*)((const char*)(g_whhbf + (size_t)(bn + r)*H + ks*128) + cc*16);
    }

    const uint32_t aoff = uA + (uint32_t)(wm*64 + (lane & 15))*LP_ROWB + (uint32_t)(lane >> 4)*16;
    const uint32_t boff = uB + (uint32_t)(wn*16 + (lane & 15))*LP_ROWB + (uint32_t)(lane >> 4)*16;

    for (int l = 0; l < L; l++) {
        if (l > 0) {
            // load h_prev tile (bf16): rows 0..127, cols ks*128..+128
            for (int i = tid; i < 128*16; i += 256) {
                int r = i >> 4, cc = i & 15;
                *(uint4*)((char*)sA + r*LP_ROWB + cc*16) =
                    *(const uint4*)((const char*)(g_catbf + (size_t)((l-1)*BATCH + r)*KCAT + ks*128) + cc*16);
            }
            __syncthreads();
            float acc[4][2][4];
#pragma unroll
            for (int ma = 0; ma < 4; ma++)
#pragma unroll
                for (int na = 0; na < 2; na++)
#pragma unroll
                    for (int q = 0; q < 4; q++) acc[ma][na][q] = 0.0f;
#pragma unroll
            for (int ka = 0; ka < 8; ka++) {
                uint32_t af[4][4], bfr[4];
#pragma unroll
                for (int ma = 0; ma < 4; ma++)
                    ldsm_x4(af[ma], aoff + ma*16*LP_ROWB + ka*32);
                ldsm_x4(bfr, boff + ka*32);
#pragma unroll
                for (int ma = 0; ma < 4; ma++) {
                    mma16816(acc[ma][0], af[ma], bfr[0], bfr[2]);
                    mma16816(acc[ma][1], af[ma], bfr[1], bfr[3]);
                }
            }
            // store fp32 partials
#pragma unroll
            for (int ma = 0; ma < 4; ma++) {
                const int r0 = wm*64 + ma*16 + g;
#pragma unroll
                for (int na = 0; na < 2; na++) {
                    const int col = bn + wn*16 + na*8 + t4*2;
                    *(float2*)&g_part[((size_t)ks*BATCH + r0)*G4 + col] =
                        make_float2(acc[ma][na][0], acc[ma][na][1]);
                    *(float2*)&g_part[((size_t)ks*BATCH + r0 + 8)*G4 + col] =
                        make_float2(acc[ma][na][2], acc[ma][na][3]);
                }
            }
            gbar(LP_NBLK);
        }
        // distributed reduce + pointwise: elem pair (b, d..d+1)
        {
            const int e0 = bid*512 + tid*2;      // = b*512 + d
            const int b = e0 >> 9, d = e0 & 511;
            float2 gv[4];
#pragma unroll
            for (int q = 0; q < 4; q++) {
                const int n = q*H + d;
                float2 v = *(const float2*)&g_xg[(size_t)(l*BATCH + b)*G4 + n];
                v.x += b_hh[n]; v.y += b_hh[n+1];
                if (l > 0) {
#pragma unroll
                    for (int s = 0; s < 4; s++) {
                        float2 p = *(const float2*)&g_part[((size_t)s*BATCH + b)*G4 + n];
                        v.x += p.x; v.y += p.y;
                    }
                }
                gv[q] = v;
            }
            float2 cp = make_float2(0.f, 0.f);
            if (l > 0) cp = *(const float2*)&g_c[b*H + d];
            float hx, hy;
            {
                float ig = sigmoid_acc(gv[0].x), fg = sigmoid_acc(gv[1].x);
                float gg = tanhf(gv[2].x),       og = sigmoid_acc(gv[3].x);
                float cn = fg*cp.x + ig*gg;
                cp.x = cn; hx = og * tanhf(cn);
            }
            {
                float ig = sigmoid_acc(gv[0].y), fg = sigmoid_acc(gv[1].y);
                float gg = tanhf(gv[2].y),       og = sigmoid_acc(gv[3].y);
                float cn = fg*cp.y + ig*gg;
                cp.y = cn; hy = og * tanhf(cn);
            }
            *(float2*)&g_c[b*H + d] = cp;
            *(float2*)&g_cat[(size_t)(l*BATCH + b)*KCAT + d] = make_float2(hx, hy);
            __nv_bfloat162 hb = __floats2bfloat162_rn(hx, hy);
            *(uint32_t*)&g_catbf[(size_t)(l*BATCH + b)*KCAT + d] = *(uint32_t*)&hb;
        }
        gbar(LP_NBLK);
    }
}

// ---------------- K4a ----------------
__global__ void featatt_kernel(const float* __restrict__ x_em,
                               const float* __restrict__ attw_w,
                               const float* __restrict__ attw_b) {
    __shared__ float sx[512][17];
    __shared__ float sh_hem[512];
    __shared__ float sh_w[512];
    __shared__ float red[16][17];
    const int tid = threadIdx.x;
    const int b  = blockIdx.y;
    const int n0 = blockIdx.x * 16;
#pragma unroll
    for (int i = 0; i < 32; i++) {
        int e = tid + i*256;
        int c = e >> 4, j = e & 15;
        sx[c][j] = x_em[((size_t)b*512 + c) * 256 + n0 + j];
    }
    sh_w[tid]     = attw_w[tid];
    sh_w[tid+256] = attw_w[tid+256];
    const float ab = attw_b[0];
    const int j  = tid % 16;
    const int cg = tid / 16;
    for (int l = 0; l < L; l++) {
        __syncthreads();
        sh_hem[tid]     = g_hem[(size_t)(l*BATCH + b) * H + tid];
        sh_hem[tid+256] = g_hem[(size_t)(l*BATCH + b) * H + tid + 256];
        __syncthreads();
        float acc = 0.0f;
#pragma unroll 8
        for (int i = 0; i < 32; i++) {
            int c = cg*32 + i;
            acc += tanh_approx(sx[c][j] + sh_hem[c]) * sh_w[c];
        }
        red[cg][j] = acc;
        __syncthreads();
        if (tid < 16) {
            float s = 0.0f;
#pragma unroll
            for (int i = 0; i < 16; i++) s += red[i][tid];
            g_fatt[(size_t)(l*BATCH + b) * HW + n0 + tid] = s + ab;
        }
    }
}

// ---------------- K4b: softmax + att (writes att as bf16 into g_catbf) ----------------
__global__ void attred_kernel(const float* __restrict__ att_x_em) {
    __shared__ float s_alpha[L][HW];
    __shared__ float s_red[8];
    __shared__ float s_val;
    const int tid = threadIdx.x;
    const int b = blockIdx.x;
    const int lane = tid & 31, wid = tid >> 5;
    for (int l = 0; l < L; l++) {
        float v = g_fatt[(size_t)(l*BATCH + b) * HW + tid];
        float m = v;
#pragma unroll
        for (int o = 16; o > 0; o >>= 1) m = fmaxf(m, __shfl_xor_sync(~0u, m, o));
        if (lane == 0) s_red[wid] = m;
        __syncthreads();
        if (tid == 0) {
            float mm = s_red[0];
#pragma unroll
            for (int i = 1; i < 8; i++) mm = fmaxf(mm, s_red[i]);
            s_val = mm;
        }
        __syncthreads();
        float e = __expf(v - s_val);
        float s = e;
#pragma unroll
        for (int o = 16; o > 0; o >>= 1) s += __shfl_xor_sync(~0u, s, o);
        if (lane == 0) s_red[wid] = s;
        __syncthreads();
        if (tid == 0) {
            float ss = 0.0f;
#pragma unroll
            for (int i = 0; i < 8; i++) ss += s_red[i];
            s_val = ss;
        }
        __syncthreads();
        s_alpha[l][tid] = e / s_val;
        __syncthreads();
    }
    float acc[L][2];
#pragma unroll
    for (int l = 0; l < L; l++) { acc[l][0] = 0.0f; acc[l][1] = 0.0f; }
    const float* axb = att_x_em + (size_t)b * HW * H;
    for (int n = 0; n < HW; n++) {
        float2 ax = *(const float2*)&axb[(size_t)n * H + 2*tid];
#pragma unroll
        for (int l = 0; l < L; l++) {
            float a = s_alpha[l][n];
            acc[l][0] += a * ax.x;
            acc[l][1] += a * ax.y;
        }
    }
#pragma unroll
    for (int l = 0; l < L; l++) {
        __nv_bfloat162 ab2 = __floats2bfloat162_rn(acc[l][0], acc[l][1]);
        *(uint32_t*)&g_catbf[(size_t)(l*BATCH + b)*KCAT + 512 + 2*tid] = *(uint32_t*)&ab2;
    }
}

// ---------------- conversions to bf16 ----------------
__global__ void conv_lin_bf(const float* __restrict__ lin_w) {
    const size_t i = ((size_t)blockIdx.x * 256 + threadIdx.x) * 4;
    const size_t row = i / KCAT;
    float4 v = (row < NCLS) ? *(const float4*)&lin_w[i] : make_float4(0.f,0.f,0.f,0.f);
    __nv_bfloat162 a = __floats2bfloat162_rn(v.x, v.y);
    __nv_bfloat162 b = __floats2bfloat162_rn(v.z, v.w);
    *(uint2*)&g_linbf[i] = make_uint2(*(uint32_t*)&a, *(uint32_t*)&b);
}
__global__ void conv_whh_bf(const float* __restrict__ W_hh) {
    const size_t i = ((size_t)blockIdx.x * 256 + threadIdx.x) * 4;
    float4 v = *(const float4*)&W_hh[i];
    __nv_bfloat162 a = __floats2bfloat162_rn(v.x, v.y);
    __nv_bfloat162 b = __floats2bfloat162_rn(v.z, v.w);
    *(uint2*)&g_whhbf[i] = make_uint2(*(uint32_t*)&a, *(uint32_t*)&b);
}

// ---------------- K5: bf16 mma.sync GEMM (unchanged from R4) ----------------
#define K5_LDS   40
#define K5_ROWB  80
#define K5_BUFB  (128*K5_ROWB)
#define K5_NCH   (KCAT/32)

__global__ void __launch_bounds__(256) k5_hmma_kernel(const float* __restrict__ bias) {
    __shared__ __nv_bfloat16 sA[2][128][K5_LDS];
    __shared__ __nv_bfloat16 sB[2][128][K5_LDS];
    const int tid  = threadIdx.x;
    const int w    = tid >> 5, lane = tid & 31;
    const int wm   = w >> 2, wn = w & 3;
    const int bm   = blockIdx.y * 128;
    const int bn   = blockIdx.x * 128;

    const uint32_t uA = smem_u32(&sA[0][0][0]);
    const uint32_t uB = smem_u32(&sB[0][0][0]);

    const int gr0 = tid >> 1;
    const int gs0 = tid & 1;
    const int gr1 = tid >> 1;
    const int gs1 = 2 + (tid & 1);
    const __nv_bfloat16* arow = g_catbf + (size_t)(bm + gr0) * KCAT;
    const __nv_bfloat16* brow = g_linbf + (size_t)(bn + gr0) * KCAT;

    float acc[4][4][4];
#pragma unroll
    for (int i = 0; i < 4; i++)
#pragma unroll
        for (int j = 0; j < 4; j++)
#pragma unroll
            for (int q = 0; q < 4; q++) acc[i][j][q] = 0.0f;

    uint4 ra[2], rb[2];
    ra[0] = *(const uint4*)(arow + gs0*8);
    ra[1] = *(const uint4*)(arow + gs1*8);
    rb[0] = *(const uint4*)(brow + gs0*8);
    rb[1] = *(const uint4*)(brow + gs1*8);
    *(uint4*)((char*)&sA[0][0][0] + gr0*K5_ROWB + gs0*16) = ra[0];
    *(uint4*)((char*)&sA[0][0][0] + gr1*K5_ROWB + gs1*16) = ra[1];
    *(uint4*)((char*)&sB[0][0][0] + gr0*K5_ROWB + gs0*16) = rb[0];
    *(uint4*)((char*)&sB[0][0][0] + gr1*K5_ROWB + gs1*16) = rb[1];

    const uint32_t aoff = (uint32_t)(wm*64 + (lane & 15)) * K5_ROWB + (uint32_t)(lane >> 4) * 16;
    const uint32_t boff = (uint32_t)(wn*32 + (lane & 15)) * K5_ROWB + (uint32_t)(lane >> 4) * 16;

    for (int c = 0; c < K5_NCH; c++) {
        __syncthreads();
        if (c + 1 < K5_NCH) {
            const int k0 = (c + 1) * 32;
            ra[0] = *(const uint4*)(arow + k0 + gs0*8);
            ra[1] = *(const uint4*)(arow + k0 + gs1*8);
            rb[0] = *(const uint4*)(brow + k0 + gs0*8);
            rb[1] = *(const uint4*)(brow + k0 + gs1*8);
        }
        const uint32_t bufA = uA + (c & 1) * K5_BUFB;
        const uint32_t bufB = uB + (c & 1) * K5_BUFB;
#pragma unroll
        for (int ka = 0; ka < 2; ka++) {
            uint32_t af[4][4];
            uint32_t bf[2][4];
#pragma unroll
            for (int ma = 0; ma < 4; ma++)
                ldsm_x4(af[ma], bufA + aoff + ma*16*K5_ROWB + ka*32);
#pragma unroll
            for (int ng = 0; ng < 2; ng++)
                ldsm_x4(bf[ng], bufB + boff + ng*16*K5_ROWB + ka*32);
#pragma unroll
            for (int ma = 0; ma < 4; ma++)
#pragma unroll
                for (int ng = 0; ng < 2; ng++) {
                    mma16816(acc[ma][ng*2+0], af[ma], bf[ng][0], bf[ng][2]);
                    mma16816(acc[ma][ng*2+1], af[ma], bf[ng][1], bf[ng][3]);
                }
        }
        if (c + 1 < K5_NCH) {
            __syncthreads();
            char* dA = (char*)&sA[(c+1)&1][0][0];
            char* dB = (char*)&sB[(c+1)&1][0][0];
            *(uint4*)(dA + gr0*K5_ROWB + gs0*16) = ra[0];
            *(uint4*)(dA + gr1*K5_ROWB + gs1*16) = ra[1];
            *(uint4*)(dB + gr0*K5_ROWB + gs0*16) = rb[0];
            *(uint4*)(dB + gr1*K5_ROWB + gs1*16) = rb[1];
        }
    }

    const int g = lane >> 2, t = lane & 3;
#pragma unroll
    for (int ma = 0; ma < 4; ma++) {
        const int r0 = bm + wm*64 + ma*16 + g;
#pragma unroll
        for (int na = 0; na < 4; na++) {
            const int col = bn + wn*32 + na*8 + t*2;
            if (col + 1 < NCLS) {
                const float2 bv = *(const float2*)&bias[col];
                *(float2*)&g_logits[(size_t)r0 * NCLS + col] =
                    make_float2(acc[ma][na][0] + bv.x, acc[ma][na][1] + bv.y);
                *(float2*)&g_logits[(size_t)(r0 + 8) * NCLS + col] =
                    make_float2(acc[ma][na][2] + bv.x, acc[ma][na][3] + bv.y);
            }
        }
    }
}

// ---------------- K6: row log-softmax ----------------
__global__ void logsoftmax_kernel(float* __restrict__ out) {
    const int m = blockIdx.x;
    const int l = m / BATCH, b = m % BATCH;
    const int tid = threadIdx.x;
    const int lane = tid & 31, wid = tid >> 5;
    __shared__ float s_red[8];
    __shared__ float s_val;
    float vals[28];
    const float* row = g_logits + (size_t)m * NCLS;
#pragma unroll
    for (int i = 0; i < 28; i++) {
        int idx = tid + i*256;
        vals[i] = (idx < NCLS) ? row[idx] : -1e30f;
    }
    float mx = -1e30f;
#pragma unroll
    for (int i = 0; i < 28; i++) mx = fmaxf(mx, vals[i]);
#pragma unroll
    for (int o = 16; o > 0; o >>= 1) mx = fmaxf(mx, __shfl_xor_sync(~0u, mx, o));
    if (lane == 0) s_red[wid] = mx;
    __syncthreads();
    if (tid == 0) {
        float mm = s_red[0];
#pragma unroll
        for (int i = 1; i < 8; i++) mm = fmaxf(mm, s_red[i]);
        s_val = mm;
    }
    __syncthreads();
    const float mall = s_val;
    float sum = 0.0f;
#pragma unroll
    for (int i = 0; i < 28; i++) sum += __expf(vals[i] - mall);
#pragma unroll
    for (int o = 16; o > 0; o >>= 1) sum += __shfl_xor_sync(~0u, sum, o);
    if (lane == 0) s_red[wid] = sum;
    __syncthreads();
    if (tid == 0) {
        float ss = 0.0f;
#pragma unroll
        for (int i = 0; i < 8; i++) ss += s_red[i];
        s_val = ss;
    }
    __syncthreads();
    const float lse = mall + logf(s_val);
    float* orow = out + ((size_t)b * L + l) * NCLS;
#pragma unroll
    for (int i = 0; i < 28; i++) {
        int idx = tid + i*256;
        if (idx < NCLS) orow[idx] = vals[i] - lse;
    }
}

// ---------------- launch ----------------
extern "C" void kernel_launch(void* const* d_in, const int* in_sizes, int n_in,
                              void* d_out, int out_size) {
    const float* hidden_en = (const float*)d_in[0];
    const float* x_em      = (const float*)d_in[1];
    const float* att_x_em  = (const float*)d_in[2];
    const int*   target    = (const int*)  d_in[3];
    const float* embed_w = (const float*)d_in[6];
    const float* W_ih    = (const float*)d_in[7];
    const float* W_hh    = (const float*)d_in[8];
    const float* b_ih    = (const float*)d_in[9];
    const float* b_hh    = (const float*)d_in[10];
    const float* hem_w   = (const float*)d_in[11];
    const float* hem_b   = (const float*)d_in[12];
    const float* attw_w  = (const float*)d_in[13];
    const float* attw_b  = (const float*)d_in[14];
    const float* lin_w   = (const float*)d_in[15];
    const float* lin_b   = (const float*)d_in[16];
    float* out = (float*)d_out;

    void *p_xts, *p_xg, *p_cat, *p_hem;
    cudaGetSymbolAddress(&p_xts, g_xts);
    cudaGetSymbolAddress(&p_xg,  g_xg);
    cudaGetSymbolAddress(&p_cat, g_cat);
    cudaGetSymbolAddress(&p_hem, g_hem);

    const int lp_smem = (128 + 64) * LP_ROWE * 2;   // 52224 bytes
    cudaFuncSetAttribute(lstm_persist, cudaFuncAttributeMaxDynamicSharedMemorySize, lp_smem);

    // K0
    gather_kernel<<<M5, 128>>>(hidden_en, embed_w, target);

    // weight conversions (independent, early)
    conv_lin_bf<<<(NPAD*KCAT/4)/256, 256>>>(lin_w);
    conv_whh_bf<<<(G4*H/4)/256, 256>>>(W_hh);

    // K1
    sgemm2_nt_bias<<<dim3(G4/128, M5/256), 256>>>(
        (const float*)p_xts, HIDI, W_ih, HIDI, b_ih, (float*)p_xg, G4, G4, HIDI);

    // K2: persistent LSTM (all 40 steps)
    lstm_persist<<<LP_NBLK, 256, lp_smem>>>(b_hh);

    // K3
    sgemm2_nt_bias<<<dim3(H/128, M5/256), 256>>>(
        (const float*)p_cat, KCAT, hem_w, H, hem_b, (float*)p_hem, H, H, H);

    // K4a, K4b
    featatt_kernel<<<dim3(16, BATCH), 256>>>(x_em, attw_w, attw_b);
    attred_kernel<<<BATCH, 256>>>(att_x_em);

    // K5
    k5_hmma_kernel<<<dim3(NPAD/128, M5/128), 256>>>(lin_b);

    // K6
    logsoftmax_kernel<<<M5, 256>>>(out);
}

// round 6
// speedup vs baseline: 3.6524x; 1.3390x over previous
#include <cuda_runtime.h>
#include <cuda_bf16.h>
#include <math.h>
#include <cstdint>

#define L      40
#define BATCH  128
#define HIDI   512
#define H      512
#define G4     2048
#define NCLS   7000
#define NPAD   7040
#define HW     256
#define M5     (L*BATCH)   /* 5120 */
#define KCAT   1024

// ---------------- scratch (static device globals: no allocation) ----------------
__device__ float g_xg [M5*G4];
__device__ float g_hem[M5*H];
__device__ float g_fatt[M5*HW];
__device__ float g_c  [BATCH*H];
__device__ float g_part[4*BATCH*G4];             // LSTM k-split partials
__device__ float g_logits[(size_t)M5*NCLS];
__device__ __nv_bfloat16 g_xtsbf[M5*HIDI];
__device__ __nv_bfloat16 g_catbf[(size_t)M5*KCAT];   // h | att, bf16
__device__ __nv_bfloat16 g_linbf[(size_t)NPAD*KCAT];
__device__ __nv_bfloat16 g_whhbf[G4*H];
__device__ __nv_bfloat16 g_wihbf[G4*HIDI];
__device__ __nv_bfloat16 g_hemwbf[H*H];
__device__ unsigned int g_bar_cnt;
__device__ volatile unsigned int g_bar_gen;

__device__ __forceinline__ float tanh_approx(float x) {
    float y; asm("tanh.approx.f32 %0, %1;" : "=f"(y) : "f"(x)); return y;
}
__device__ __forceinline__ float sigmoid_acc(float x) { return 1.0f / (1.0f + expf(-x)); }

__device__ __forceinline__ uint32_t smem_u32(const void* p) {
    uint32_t a;
    asm("{ .reg .u64 t; cvta.to.shared.u64 t, %1; cvt.u32.u64 %0, t; }" : "=r"(a) : "l"(p));
    return a;
}
__device__ __forceinline__ void ldsm_x4(uint32_t* r, uint32_t addr) {
    asm volatile("ldmatrix.sync.aligned.m8n8.x4.shared.b16 {%0,%1,%2,%3}, [%4];"
                 : "=r"(r[0]), "=r"(r[1]), "=r"(r[2]), "=r"(r[3]) : "r"(addr));
}
__device__ __forceinline__ void mma16816(float* c, const uint32_t* a, uint32_t b0, uint32_t b1) {
    asm volatile("mma.sync.aligned.m16n8k16.row.col.f32.bf16.bf16.f32 "
                 "{%0,%1,%2,%3}, {%4,%5,%6,%7}, {%8,%9}, {%0,%1,%2,%3};"
                 : "+f"(c[0]), "+f"(c[1]), "+f"(c[2]), "+f"(c[3])
                 : "r"(a[0]), "r"(a[1]), "r"(a[2]), "r"(a[3]), "r"(b0), "r"(b1));
}

// grid-wide software barrier (all CTAs co-resident; count self-resets)
__device__ __forceinline__ void gbar(int nblk) {
    __syncthreads();
    if (threadIdx.x == 0) {
        __threadfence();
        unsigned int gen = g_bar_gen;
        if (atomicAdd(&g_bar_cnt, 1u) == (unsigned)(nblk - 1)) {
            g_bar_cnt = 0;
            __threadfence();
            g_bar_gen = gen + 1;
        } else {
            while (g_bar_gen == gen) { __nanosleep(32); }
        }
        __threadfence();
    }
    __syncthreads();
}

// ---------------- K0: gather teacher-forced inputs (bf16 out) ----------------
__global__ void gather_kernel(const float* __restrict__ hidden_en,
                              const float* __restrict__ embed_w,
                              const int*   __restrict__ target) {
    const int m = blockIdx.x;
    const int l = m / BATCH, b = m % BATCH;
    const int k = threadIdx.x * 4;
    const float* src = (l == 0)
        ? (hidden_en + (size_t)b * HIDI)
        : (embed_w   + (size_t)target[b * L + (l - 1)] * HIDI);
    float4 v = *(const float4*)&src[k];
    __nv_bfloat162 a = __floats2bfloat162_rn(v.x, v.y);
    __nv_bfloat162 c = __floats2bfloat162_rn(v.z, v.w);
    *(uint2*)&g_xtsbf[(size_t)m * HIDI + k] = make_uint2(*(uint32_t*)&a, *(uint32_t*)&c);
}

// ---------------- generic bf16 HMMA GEMM: C = bias + A_bf @ B_bf^T ----------------
// CTA 128x128, K-chunk 32, double-buffered 80B-padded SMEM rows, 8 warps 2x4,
// warp tile 64x32 via m16n8k16, fp32 accum. M%128==0, N%128==0, K%32==0,
// lda/ldb %8==0; nlim guards store columns (for NCLS).
#define HG_LDS   40
#define HG_ROWB  80
#define HG_BUFB  (128*HG_ROWB)

__global__ void __launch_bounds__(256) hgemm_nt_bias(
        const __nv_bfloat16* __restrict__ A, int lda,
        const __nv_bfloat16* __restrict__ B, int ldb,
        const float* __restrict__ bias,
        float* __restrict__ C, int ldc,
        int nlim, int K) {
    __shared__ __nv_bfloat16 sA[2][128][HG_LDS];
    __shared__ __nv_bfloat16 sB[2][128][HG_LDS];
    const int tid  = threadIdx.x;
    const int w    = tid >> 5, lane = tid & 31;
    const int wm   = w >> 2, wn = w & 3;
    const int bm   = blockIdx.y * 128;
    const int bn   = blockIdx.x * 128;
    const int nch  = K >> 5;

    const uint32_t uA = smem_u32(&sA[0][0][0]);
    const uint32_t uB = smem_u32(&sB[0][0][0]);

    const int gr0 = tid >> 1;
    const int gs0 = tid & 1;
    const int gs1 = 2 + (tid & 1);
    const __nv_bfloat16* arow = A + (size_t)(bm + gr0) * lda;
    const __nv_bfloat16* brow = B + (size_t)(bn + gr0) * ldb;

    float acc[4][4][4];
#pragma unroll
    for (int i = 0; i < 4; i++)
#pragma unroll
        for (int j = 0; j < 4; j++)
#pragma unroll
            for (int q = 0; q < 4; q++) acc[i][j][q] = 0.0f;

    uint4 ra[2], rb[2];
    ra[0] = *(const uint4*)(arow + gs0*8);
    ra[1] = *(const uint4*)(arow + gs1*8);
    rb[0] = *(const uint4*)(brow + gs0*8);
    rb[1] = *(const uint4*)(brow + gs1*8);
    *(uint4*)((char*)&sA[0][0][0] + gr0*HG_ROWB + gs0*16) = ra[0];
    *(uint4*)((char*)&sA[0][0][0] + gr0*HG_ROWB + gs1*16) = ra[1];
    *(uint4*)((char*)&sB[0][0][0] + gr0*HG_ROWB + gs0*16) = rb[0];
    *(uint4*)((char*)&sB[0][0][0] + gr0*HG_ROWB + gs1*16) = rb[1];

    const uint32_t aoff = (uint32_t)(wm*64 + (lane & 15)) * HG_ROWB + (uint32_t)(lane >> 4) * 16;
    const uint32_t boff = (uint32_t)(wn*32 + (lane & 15)) * HG_ROWB + (uint32_t)(lane >> 4) * 16;

    for (int c = 0; c < nch; c++) {
        __syncthreads();
        if (c + 1 < nch) {
            const int k0 = (c + 1) * 32;
            ra[0] = *(const uint4*)(arow + k0 + gs0*8);
            ra[1] = *(const uint4*)(arow + k0 + gs1*8);
            rb[0] = *(const uint4*)(brow + k0 + gs0*8);
            rb[1] = *(const uint4*)(brow + k0 + gs1*8);
        }
        const uint32_t bufA = uA + (c & 1) * HG_BUFB;
        const uint32_t bufB = uB + (c & 1) * HG_BUFB;
#pragma unroll
        for (int ka = 0; ka < 2; ka++) {
            uint32_t af[4][4];
            uint32_t bf[2][4];
#pragma unroll
            for (int ma = 0; ma < 4; ma++)
                ldsm_x4(af[ma], bufA + aoff + ma*16*HG_ROWB + ka*32);
#pragma unroll
            for (int ng = 0; ng < 2; ng++)
                ldsm_x4(bf[ng], bufB + boff + ng*16*HG_ROWB + ka*32);
#pragma unroll
            for (int ma = 0; ma < 4; ma++)
#pragma unroll
                for (int ng = 0; ng < 2; ng++) {
                    mma16816(acc[ma][ng*2+0], af[ma], bf[ng][0], bf[ng][2]);
                    mma16816(acc[ma][ng*2+1], af[ma], bf[ng][1], bf[ng][3]);
                }
        }
        if (c + 1 < nch) {
            __syncthreads();
            char* dA = (char*)&sA[(c+1)&1][0][0];
            char* dB = (char*)&sB[(c+1)&1][0][0];
            *(uint4*)(dA + gr0*HG_ROWB + gs0*16) = ra[0];
            *(uint4*)(dA + gr0*HG_ROWB + gs1*16) = ra[1];
            *(uint4*)(dB + gr0*HG_ROWB + gs0*16) = rb[0];
            *(uint4*)(dB + gr0*HG_ROWB + gs1*16) = rb[1];
        }
    }

    const int g = lane >> 2, t = lane & 3;
#pragma unroll
    for (int ma = 0; ma < 4; ma++) {
        const int r0 = bm + wm*64 + ma*16 + g;
#pragma unroll
        for (int na = 0; na < 4; na++) {
            const int col = bn + wn*32 + na*8 + t*2;
            if (col + 1 < nlim) {
                const float2 bv = *(const float2*)&bias[col];
                *(float2*)&C[(size_t)r0 * ldc + col] =
                    make_float2(acc[ma][na][0] + bv.x, acc[ma][na][1] + bv.y);
                *(float2*)&C[(size_t)(r0 + 8) * ldc + col] =
                    make_float2(acc[ma][na][2] + bv.x, acc[ma][na][3] + bv.y);
            }
        }
    }
}

// ---------------- persistent LSTM (unchanged logic; fp32 h store dropped) ----------------
#define LP_NBLK 128
#define LP_ROWE 136
#define LP_ROWB 272

__global__ void __launch_bounds__(256) lstm_persist(const float* __restrict__ b_hh) {
    extern __shared__ __nv_bfloat16 sm[];
    __nv_bfloat16* sA = sm;
    __nv_bfloat16* sB = sm + 128*LP_ROWE;
    const int tid = threadIdx.x;
    const int w = tid >> 5, lane = tid & 31;
    const int wm = w >> 2, wn = w & 3;
    const int bid = blockIdx.x;
    const int bn = (bid & 31) * 64;
    const int ks = bid >> 5;
    const uint32_t uA = smem_u32(sA), uB = smem_u32(sB);
    const int g = lane >> 2, t4 = lane & 3;

    for (int i = tid; i < 64*16; i += 256) {
        int r = i >> 4, cc = i & 15;
        *(uint4*)((char*)sB + r*LP_ROWB + cc*16) =
            *(const uint4*)((const char*)(g_whhbf + (size_t)(bn + r)*H + ks*128) + cc*16);
    }

    const uint32_t aoff = uA + (uint32_t)(wm*64 + (lane & 15))*LP_ROWB + (uint32_t)(lane >> 4)*16;
    const uint32_t boff = uB + (uint32_t)(wn*16 + (lane & 15))*LP_ROWB + (uint32_t)(lane >> 4)*16;

    for (int l = 0; l < L; l++) {
        if (l > 0) {
            for (int i = tid; i < 128*16; i += 256) {
                int r = i >> 4, cc = i & 15;
                *(uint4*)((char*)sA + r*LP_ROWB + cc*16) =
                    *(const uint4*)((const char*)(g_catbf + (size_t)((l-1)*BATCH + r)*KCAT + ks*128) + cc*16);
            }
            __syncthreads();
            float acc[4][2][4];
#pragma unroll
            for (int ma = 0; ma < 4; ma++)
#pragma unroll
                for (int na = 0; na < 2; na++)
#pragma unroll
                    for (int q = 0; q < 4; q++) acc[ma][na][q] = 0.0f;
#pragma unroll
            for (int ka = 0; ka < 8; ka++) {
                uint32_t af[4][4], bfr[4];
#pragma unroll
                for (int ma = 0; ma < 4; ma++)
                    ldsm_x4(af[ma], aoff + ma*16*LP_ROWB + ka*32);
                ldsm_x4(bfr, boff + ka*32);
#pragma unroll
                for (int ma = 0; ma < 4; ma++) {
                    mma16816(acc[ma][0], af[ma], bfr[0], bfr[2]);
                    mma16816(acc[ma][1], af[ma], bfr[1], bfr[3]);
                }
            }
#pragma unroll
            for (int ma = 0; ma < 4; ma++) {
                const int r0 = wm*64 + ma*16 + g;
#pragma unroll
                for (int na = 0; na < 2; na++) {
                    const int col = bn + wn*16 + na*8 + t4*2;
                    *(float2*)&g_part[((size_t)ks*BATCH + r0)*G4 + col] =
                        make_float2(acc[ma][na][0], acc[ma][na][1]);
                    *(float2*)&g_part[((size_t)ks*BATCH + r0 + 8)*G4 + col] =
                        make_float2(acc[ma][na][2], acc[ma][na][3]);
                }
            }
            gbar(LP_NBLK);
        }
        {
            const int e0 = bid*512 + tid*2;
            const int b = e0 >> 9, d = e0 & 511;
            float2 gv[4];
#pragma unroll
            for (int q = 0; q < 4; q++) {
                const int n = q*H + d;
                float2 v = *(const float2*)&g_xg[(size_t)(l*BATCH + b)*G4 + n];
                v.x += b_hh[n]; v.y += b_hh[n+1];
                if (l > 0) {
#pragma unroll
                    for (int s = 0; s < 4; s++) {
                        float2 p = *(const float2*)&g_part[((size_t)s*BATCH + b)*G4 + n];
                        v.x += p.x; v.y += p.y;
                    }
                }
                gv[q] = v;
            }
            float2 cp = make_float2(0.f, 0.f);
            if (l > 0) cp = *(const float2*)&g_c[b*H + d];
            float hx, hy;
            {
                float ig = sigmoid_acc(gv[0].x), fg = sigmoid_acc(gv[1].x);
                float gg = tanhf(gv[2].x),       og = sigmoid_acc(gv[3].x);
                float cn = fg*cp.x + ig*gg;
                cp.x = cn; hx = og * tanhf(cn);
            }
            {
                float ig = sigmoid_acc(gv[0].y), fg = sigmoid_acc(gv[1].y);
                float gg = tanhf(gv[2].y),       og = sigmoid_acc(gv[3].y);
                float cn = fg*cp.y + ig*gg;
                cp.y = cn; hy = og * tanhf(cn);
            }
            *(float2*)&g_c[b*H + d] = cp;
            __nv_bfloat162 hb = __floats2bfloat162_rn(hx, hy);
            *(uint32_t*)&g_catbf[(size_t)(l*BATCH + b)*KCAT + d] = *(uint32_t*)&hb;
        }
        gbar(LP_NBLK);
    }
}

// ---------------- K4a ----------------
__global__ void featatt_kernel(const float* __restrict__ x_em,
                               const float* __restrict__ attw_w,
                               const float* __restrict__ attw_b) {
    __shared__ float sx[512][17];
    __shared__ float sh_hem[512];
    __shared__ float sh_w[512];
    __shared__ float red[16][17];
    const int tid = threadIdx.x;
    const int b  = blockIdx.y;
    const int n0 = blockIdx.x * 16;
#pragma unroll
    for (int i = 0; i < 32; i++) {
        int e = tid + i*256;
        int c = e >> 4, j = e & 15;
        sx[c][j] = x_em[((size_t)b*512 + c) * 256 + n0 + j];
    }
    sh_w[tid]     = attw_w[tid];
    sh_w[tid+256] = attw_w[tid+256];
    const float ab = attw_b[0];
    const int j  = tid % 16;
    const int cg = tid / 16;
    for (int l = 0; l < L; l++) {
        __syncthreads();
        sh_hem[tid]     = g_hem[(size_t)(l*BATCH + b) * H + tid];
        sh_hem[tid+256] = g_hem[(size_t)(l*BATCH + b) * H + tid + 256];
        __syncthreads();
        float acc = 0.0f;
#pragma unroll 8
        for (int i = 0; i < 32; i++) {
            int c = cg*32 + i;
            acc += tanh_approx(sx[c][j] + sh_hem[c]) * sh_w[c];
        }
        red[cg][j] = acc;
        __syncthreads();
        if (tid < 16) {
            float s = 0.0f;
#pragma unroll
            for (int i = 0; i < 16; i++) s += red[i][tid];
            g_fatt[(size_t)(l*BATCH + b) * HW + n0 + tid] = s + ab;
        }
    }
}

// ---------------- K4b ----------------
__global__ void attred_kernel(const float* __restrict__ att_x_em) {
    __shared__ float s_alpha[L][HW];
    __shared__ float s_red[8];
    __shared__ float s_val;
    const int tid = threadIdx.x;
    const int b = blockIdx.x;
    const int lane = tid & 31, wid = tid >> 5;
    for (int l = 0; l < L; l++) {
        float v = g_fatt[(size_t)(l*BATCH + b) * HW + tid];
        float m = v;
#pragma unroll
        for (int o = 16; o > 0; o >>= 1) m = fmaxf(m, __shfl_xor_sync(~0u, m, o));
        if (lane == 0) s_red[wid] = m;
        __syncthreads();
        if (tid == 0) {
            float mm = s_red[0];
#pragma unroll
            for (int i = 1; i < 8; i++) mm = fmaxf(mm, s_red[i]);
            s_val = mm;
        }
        __syncthreads();
        float e = __expf(v - s_val);
        float s = e;
#pragma unroll
        for (int o = 16; o > 0; o >>= 1) s += __shfl_xor_sync(~0u, s, o);
        if (lane == 0) s_red[wid] = s;
        __syncthreads();
        if (tid == 0) {
            float ss = 0.0f;
#pragma unroll
            for (int i = 0; i < 8; i++) ss += s_red[i];
            s_val = ss;
        }
        __syncthreads();
        s_alpha[l][tid] = e / s_val;
        __syncthreads();
    }
    float acc[L][2];
#pragma unroll
    for (int l = 0; l < L; l++) { acc[l][0] = 0.0f; acc[l][1] = 0.0f; }
    const float* axb = att_x_em + (size_t)b * HW * H;
    for (int n = 0; n < HW; n++) {
        float2 ax = *(const float2*)&axb[(size_t)n * H + 2*tid];
#pragma unroll
        for (int l = 0; l < L; l++) {
            float a = s_alpha[l][n];
            acc[l][0] += a * ax.x;
            acc[l][1] += a * ax.y;
        }
    }
#pragma unroll
    for (int l = 0; l < L; l++) {
        __nv_bfloat162 ab2 = __floats2bfloat162_rn(acc[l][0], acc[l][1]);
        *(uint32_t*)&g_catbf[(size_t)(l*BATCH + b)*KCAT + 512 + 2*tid] = *(uint32_t*)&ab2;
    }
}

// ---------------- weight conversions to bf16 ----------------
__global__ void conv_lin_bf(const float* __restrict__ lin_w) {
    const size_t i = ((size_t)blockIdx.x * 256 + threadIdx.x) * 4;
    const size_t row = i / KCAT;
    float4 v = (row < NCLS) ? *(const float4*)&lin_w[i] : make_float4(0.f,0.f,0.f,0.f);
    __nv_bfloat162 a = __floats2bfloat162_rn(v.x, v.y);
    __nv_bfloat162 b = __floats2bfloat162_rn(v.z, v.w);
    *(uint2*)&g_linbf[i] = make_uint2(*(uint32_t*)&a, *(uint32_t*)&b);
}
__global__ void conv_f2bf(const float* __restrict__ src, __nv_bfloat16* __restrict__ dst) {
    const size_t i = ((size_t)blockIdx.x * 256 + threadIdx.x) * 4;
    float4 v = *(const float4*)&src[i];
    __nv_bfloat162 a = __floats2bfloat162_rn(v.x, v.y);
    __nv_bfloat162 b = __floats2bfloat162_rn(v.z, v.w);
    *(uint2*)&dst[i] = make_uint2(*(uint32_t*)&a, *(uint32_t*)&b);
}

// ---------------- K6: row log-softmax ----------------
__global__ void logsoftmax_kernel(float* __restrict__ out) {
    const int m = blockIdx.x;
    const int l = m / BATCH, b = m % BATCH;
    const int tid = threadIdx.x;
    const int lane = tid & 31, wid = tid >> 5;
    __shared__ float s_red[8];
    __shared__ float s_val;
    float vals[28];
    const float* row = g_logits + (size_t)m * NCLS;
#pragma unroll
    for (int i = 0; i < 28; i++) {
        int idx = tid + i*256;
        vals[i] = (idx < NCLS) ? row[idx] : -1e30f;
    }
    float mx = -1e30f;
#pragma unroll
    for (int i = 0; i < 28; i++) mx = fmaxf(mx, vals[i]);
#pragma unroll
    for (int o = 16; o > 0; o >>= 1) mx = fmaxf(mx, __shfl_xor_sync(~0u, mx, o));
    if (lane == 0) s_red[wid] = mx;
    __syncthreads();
    if (tid == 0) {
        float mm = s_red[0];
#pragma unroll
        for (int i = 1; i < 8; i++) mm = fmaxf(mm, s_red[i]);
        s_val = mm;
    }
    __syncthreads();
    const float mall = s_val;
    float sum = 0.0f;
#pragma unroll
    for (int i = 0; i < 28; i++) sum += __expf(vals[i] - mall);
#pragma unroll
    for (int o = 16; o > 0; o >>= 1) sum += __shfl_xor_sync(~0u, sum, o);
    if (lane == 0) s_red[wid] = sum;
    __syncthreads();
    if (tid == 0) {
        float ss = 0.0f;
#pragma unroll
        for (int i = 0; i < 8; i++) ss += s_red[i];
        s_val = ss;
    }
    __syncthreads();
    const float lse = mall + logf(s_val);
    float* orow = out + ((size_t)b * L + l) * NCLS;
#pragma unroll
    for (int i = 0; i < 28; i++) {
        int idx = tid + i*256;
        if (idx < NCLS) orow[idx] = vals[i] - lse;
    }
}

// ---------------- launch ----------------
extern "C" void kernel_launch(void* const* d_in, const int* in_sizes, int n_in,
                              void* d_out, int out_size) {
    const float* hidden_en = (const float*)d_in[0];
    const float* x_em      = (const float*)d_in[1];
    const float* att_x_em  = (const float*)d_in[2];
    const int*   target    = (const int*)  d_in[3];
    const float* embed_w = (const float*)d_in[6];
    const float* W_ih    = (const float*)d_in[7];
    const float* W_hh    = (const float*)d_in[8];
    const float* b_ih    = (const float*)d_in[9];
    const float* b_hh    = (const float*)d_in[10];
    const float* hem_w   = (const float*)d_in[11];
    const float* hem_b   = (const float*)d_in[12];
    const float* attw_w  = (const float*)d_in[13];
    const float* attw_b  = (const float*)d_in[14];
    const float* lin_w   = (const float*)d_in[15];
    const float* lin_b   = (const float*)d_in[16];
    float* out = (float*)d_out;

    void *p_xg, *p_hem, *p_xtsbf, *p_catbf, *p_linbf, *p_whhbf, *p_wihbf, *p_hemwbf, *p_logits;
    cudaGetSymbolAddress(&p_xg,     g_xg);
    cudaGetSymbolAddress(&p_hem,    g_hem);
    cudaGetSymbolAddress(&p_xtsbf,  g_xtsbf);
    cudaGetSymbolAddress(&p_catbf,  g_catbf);
    cudaGetSymbolAddress(&p_linbf,  g_linbf);
    cudaGetSymbolAddress(&p_whhbf,  g_whhbf);
    cudaGetSymbolAddress(&p_wihbf,  g_wihbf);
    cudaGetSymbolAddress(&p_hemwbf, g_hemwbf);
    cudaGetSymbolAddress(&p_logits, g_logits);

    const int lp_smem = (128 + 64) * LP_ROWE * 2;
    cudaFuncSetAttribute(lstm_persist, cudaFuncAttributeMaxDynamicSharedMemorySize, lp_smem);

    // K0 (bf16 out)
    gather_kernel<<<M5, 128>>>(hidden_en, embed_w, target);

    // weight conversions
    conv_lin_bf<<<(NPAD*KCAT/4)/256, 256>>>(lin_w);
    conv_f2bf<<<(G4*H/4)/256, 256>>>(W_hh, (__nv_bfloat16*)p_whhbf);
    conv_f2bf<<<(G4*HIDI/4)/256, 256>>>(W_ih, (__nv_bfloat16*)p_wihbf);
    conv_f2bf<<<(H*H/4)/256, 256>>>(hem_w, (__nv_bfloat16*)p_hemwbf);

    // K1: xg = xts @ W_ih^T + b_ih  [5120 x 2048], K=512 (HMMA)
    hgemm_nt_bias<<<dim3(G4/128, M5/128), 256>>>(
        (const __nv_bfloat16*)p_xtsbf, HIDI, (const __nv_bfloat16*)p_wihbf, HIDI,
        b_ih, (float*)p_xg, G4, G4, HIDI);

    // K2: persistent LSTM
    lstm_persist<<<LP_NBLK, 256, lp_smem>>>(b_hh);

    // K3: hem = h @ hem_w^T + hem_b  [5120 x 512], K=512 (HMMA, A = g_catbf cols 0..511)
    hgemm_nt_bias<<<dim3(H/128, M5/128), 256>>>(
        (const __nv_bfloat16*)p_catbf, KCAT, (const __nv_bfloat16*)p_hemwbf, H,
        hem_b, (float*)p_hem, H, H, H);

    // K4a, K4b
    featatt_kernel<<<dim3(16, BATCH), 256>>>(x_em, attw_w, attw_b);
    attred_kernel<<<BATCH, 256>>>(att_x_em);

    // K5: logits [5120 x 7000], K=1024 (HMMA)
    hgemm_nt_bias<<<dim3(NPAD/128, M5/128), 256>>>(
        (const __nv_bfloat16*)p_catbf, KCAT, (const __nv_bfloat16*)p_linbf, KCAT,
        lin_b, (float*)p_logits, NCLS, NCLS, KCAT);

    // K6
    logsoftmax_kernel<<<M5, 256>>>(out);
}